// round 8
// baseline (speedup 1.0000x reference)
#include <cuda_runtime.h>
#include <cstdint>
#include <math.h>

// True problem dims: T=4096, I=101, H=1000, L=4
#define TDIM 4096
#define IDIM 101
#define HENC 1000
#define LNUM 4
#define GE (4*HENC)   // 4000 encoder gate dim
#define GD (4*IDIM)   // 404 decoder gate dim

// ---------------- scratch (device globals; no allocation) ----------------
__device__ float g_hEnc[TDIM * HENC];
__device__ float g_cEnc[TDIM * HENC];
__device__ float g_enc [TDIM * HENC];
__device__ float g_gatesE[TDIM * GE];
__device__ float g_hDec[TDIM * IDIM];
__device__ float g_cDec[TDIM * IDIM];
__device__ float g_gatesD[TDIM * GD];

__device__ __forceinline__ float sigf(float x) { return 1.0f / (1.0f + expf(-x)); }

// ---------------- GEMM: C[M,N] (+)= A[M,K] @ B[N,K]^T ----------------
// M multiple of 128 (grid.y), N/K arbitrary (guarded). Row-major everywhere.
template<int BETA>
__global__ __launch_bounds__(256, 2)
void gemm_nt(float* __restrict__ C, const float* __restrict__ A,
             const float* __restrict__ B, int N, int K) {
    __shared__ float As[16][132];   // +4 pad keeps 16B alignment & breaks conflicts
    __shared__ float Bs[16][132];
    const int tid = threadIdx.x;
    const int tx = tid & 15, ty = tid >> 4;
    const int m0 = blockIdx.y * 128;
    const int n0 = blockIdx.x * 128;

    unsigned long long acc[8][4];
    #pragma unroll
    for (int i = 0; i < 8; ++i)
        #pragma unroll
        for (int j = 0; j < 4; ++j) acc[i][j] = 0ull;

    for (int k0 = 0; k0 < K; k0 += 16) {
        #pragma unroll
        for (int j = 0; j < 8; ++j) {
            int idx = tid + j * 256;
            int m = idx >> 4;          // 0..127
            int k = idx & 15;
            int gk = k0 + k;
            As[k][m] = (gk < K) ? A[(m0 + m) * K + gk] : 0.0f;
            Bs[k][m] = (gk < K && (n0 + m) < N) ? B[(n0 + m) * K + gk] : 0.0f;
        }
        __syncthreads();
        #pragma unroll
        for (int kk = 0; kk < 16; ++kk) {
            float4 a0 = *(const float4*)&As[kk][ty * 4];
            float4 a1 = *(const float4*)&As[kk][64 + ty * 4];
            ulonglong2 bq0 = *(const ulonglong2*)&Bs[kk][tx * 4];
            ulonglong2 bq1 = *(const ulonglong2*)&Bs[kk][64 + tx * 4];
            unsigned long long bp[4] = {bq0.x, bq0.y, bq1.x, bq1.y};
            float am[8] = {a0.x, a0.y, a0.z, a0.w, a1.x, a1.y, a1.z, a1.w};
            #pragma unroll
            for (int i = 0; i < 8; ++i) {
                unsigned long long ad;
                asm("mov.b64 %0, {%1, %1};" : "=l"(ad) : "f"(am[i]));
                #pragma unroll
                for (int j = 0; j < 4; ++j)
                    asm("fma.rn.f32x2 %0, %1, %2, %0;"
                        : "+l"(acc[i][j]) : "l"(ad), "l"(bp[j]));
            }
        }
        __syncthreads();
    }

    #pragma unroll
    for (int i = 0; i < 8; ++i) {
        int row = m0 + ((i < 4) ? ty * 4 + i : 64 + ty * 4 + (i - 4));
        float* Cr = C + (size_t)row * N;
        #pragma unroll
        for (int j = 0; j < 4; ++j) {
            int n = n0 + ((j < 2) ? tx * 4 + j * 2 : 64 + tx * 4 + (j - 2) * 2);
            float lo, hi;
            asm("mov.b64 {%0, %1}, %2;" : "=f"(lo), "=f"(hi) : "l"(acc[i][j]));
            if (n < N)     { if (BETA) Cr[n]     += lo; else Cr[n]     = lo; }
            if (n + 1 < N) { if (BETA) Cr[n + 1] += hi; else Cr[n + 1] = hi; }
        }
    }
}

// ---------------- LSTM cell update (bias added here) ----------------
template<int CZERO>
__global__ void cell_kernel(const float* __restrict__ gates,
                            const float* __restrict__ bih,
                            const float* __restrict__ bhh,
                            float* __restrict__ h, float* __restrict__ c,
                            int H, int total) {
    int idx = blockIdx.x * blockDim.x + threadIdx.x;
    if (idx >= total) return;
    int m = idx / H, n = idx - m * H;
    const float* g = gates + (size_t)m * 4 * H;
    float gi = g[n]         + bih[n]         + bhh[n];
    float gf = g[H + n]     + bih[H + n]     + bhh[H + n];
    float gg = g[2 * H + n] + bih[2 * H + n] + bhh[2 * H + n];
    float go = g[3 * H + n] + bih[3 * H + n] + bhh[3 * H + n];
    float cc = CZERO ? 0.0f : c[idx];
    cc = sigf(gf) * cc + sigf(gi) * tanhf(gg);
    float hh = sigf(go) * tanhf(cc);
    c[idx] = cc;
    h[idx] = hh;
}

__global__ void relu_kernel(const float* __restrict__ in, float* __restrict__ o, int n) {
    int i = blockIdx.x * blockDim.x + threadIdx.x;
    if (i < n) o[i] = fmaxf(in[i], 0.0f);
}

// ---------------- log_softmax: warp per row over 101 cols ----------------
__global__ void lsm_kernel(const float* __restrict__ h, float* __restrict__ out) {
    int w = (blockIdx.x * blockDim.x + threadIdx.x) >> 5;
    int lane = threadIdx.x & 31;
    if (w >= TDIM) return;
    const float* r = h + (size_t)w * IDIM;
    float v[4];
    float m = -1e30f;
    #pragma unroll
    for (int it = 0; it < 4; ++it) {
        int n = lane + 32 * it;
        v[it] = (n < IDIM) ? r[n] : -1e30f;
        m = fmaxf(m, v[it]);
    }
    #pragma unroll
    for (int o = 16; o; o >>= 1) m = fmaxf(m, __shfl_xor_sync(0xffffffffu, m, o));
    float s = 0.0f;
    #pragma unroll
    for (int it = 0; it < 4; ++it) s += expf(v[it] - m);
    #pragma unroll
    for (int o = 16; o; o >>= 1) s += __shfl_xor_sync(0xffffffffu, s, o);
    float L = m + logf(s);
    #pragma unroll
    for (int it = 0; it < 4; ++it) {
        int n = lane + 32 * it;
        if (n < IDIM) out[(size_t)w * IDIM + n] = v[it] - L;
    }
}

extern "C" void kernel_launch(void* const* d_in, const int* in_sizes, int n_in,
                              void* d_out, int out_size) {
    // ---- Resolve inputs by TRUE element counts ----
    // x        = 4096*101        = 413,696    (unique)
    // enc_Wih  = 4*4000*101      = 1,616,000  (collides with dec_Wih)
    // enc_Whh  = 4*4000*1000     = 16,000,000 (unique)
    // enc_bih/bhh = 16,000 each  (pair, summed -> order irrelevant)
    // dec_Wih  = 4*404*1000      = 1,616,000  (collides with enc_Wih)
    // dec_Whh  = 4*404*101       = 163,216    (unique)
    // dec_bih/bhh = 1,616 each   (pair, summed -> order irrelevant)
    int ix = -1, ieWhh = -1, idWhh = -1;
    int iEB[2] = {0, 0}, nEB = 0;      // 16000
    int iDB[2] = {0, 0}, nDB = 0;      // 1616
    int iWI[2] = {0, 0}, nWI = 0;      // 1,616,000
    for (int i = 0; i < n_in; ++i) {
        const int s = in_sizes[i];
        if (s == 413696) ix = i;
        else if (s == 16000000) ieWhh = i;
        else if (s == 163216) idWhh = i;
        else if (s == 16000 && nEB < 2) iEB[nEB++] = i;
        else if (s == 1616 && nDB < 2) iDB[nDB++] = i;
        else if (s == 1616000 && nWI < 2) iWI[nWI++] = i;
    }
    // eWih/dWih disambiguation: adjacency (either side) to the unique matching Whh.
    bool a0e = (iWI[0] == ieWhh - 1) || (iWI[0] == ieWhh + 1);
    bool a1e = (iWI[1] == ieWhh - 1) || (iWI[1] == ieWhh + 1);
    bool a0d = (iWI[0] == idWhh - 1) || (iWI[0] == idWhh + 1);
    bool a1d = (iWI[1] == idWhh - 1) || (iWI[1] == idWhh + 1);
    int ieWih, idWih;
    if (a0e && !a1e)      { ieWih = iWI[0]; idWih = iWI[1]; }
    else if (a1e && !a0e) { ieWih = iWI[1]; idWih = iWI[0]; }
    else if (a0d && !a1d) { idWih = iWI[0]; ieWih = iWI[1]; }
    else if (a1d && !a0d) { idWih = iWI[1]; ieWih = iWI[0]; }
    else                  { ieWih = iWI[0]; idWih = iWI[1]; }
    if (ix < 0) ix = 0;
    if (ieWhh < 0) ieWhh = 0;
    if (idWhh < 0) idWhh = 0;

    const float* x    = (const float*)d_in[ix];
    const float* eWih = (const float*)d_in[ieWih];
    const float* eWhh = (const float*)d_in[ieWhh];
    const float* ebih = (const float*)d_in[iEB[0]];
    const float* ebhh = (const float*)d_in[iEB[1]];
    const float* dWih = (const float*)d_in[idWih];
    const float* dWhh = (const float*)d_in[idWhh];
    const float* dbih = (const float*)d_in[iDB[0]];
    const float* dbhh = (const float*)d_in[iDB[1]];
    float* out = (float*)d_out;

    // scratch pointers
    float *hEnc, *cEnc, *enc, *gatesE, *hDec, *cDec, *gatesD;
    cudaGetSymbolAddress((void**)&hEnc,   g_hEnc);
    cudaGetSymbolAddress((void**)&cEnc,   g_cEnc);
    cudaGetSymbolAddress((void**)&enc,    g_enc);
    cudaGetSymbolAddress((void**)&gatesE, g_gatesE);
    cudaGetSymbolAddress((void**)&hDec,   g_hDec);
    cudaGetSymbolAddress((void**)&cDec,   g_cDec);
    cudaGetSymbolAddress((void**)&gatesD, g_gatesD);

    const dim3 gridE((GE + 127) / 128, TDIM / 128);   // 32 x 32
    const dim3 gridD((GD + 127) / 128, TDIM / 128);   // 4 x 32
    const int cellEB = (TDIM * HENC + 255) / 256;
    const int cellDB = (TDIM * IDIM + 255) / 256;

    // ---------------- Encoder ----------------
    // layer 0: h=c=0 -> gates = x @ Wih^T only
    gemm_nt<0><<<gridE, 256>>>(gatesE, x, eWih, GE, IDIM);
    cell_kernel<1><<<cellEB, 256>>>(gatesE, ebih, ebhh, hEnc, cEnc, HENC, TDIM * HENC);
    for (int l = 1; l < LNUM; ++l) {
        gemm_nt<0><<<gridE, 256>>>(gatesE, x, eWih + (size_t)l * GE * IDIM, GE, IDIM);
        gemm_nt<1><<<gridE, 256>>>(gatesE, hEnc, eWhh + (size_t)l * GE * HENC, GE, HENC);
        cell_kernel<0><<<cellEB, 256>>>(gatesE, ebih + l * GE, ebhh + l * GE,
                                        hEnc, cEnc, HENC, TDIM * HENC);
    }
    relu_kernel<<<(TDIM * HENC + 255) / 256, 256>>>(hEnc, enc, TDIM * HENC);

    // ---------------- Decoder ----------------
    gemm_nt<0><<<gridD, 256>>>(gatesD, enc, dWih, GD, HENC);
    cell_kernel<1><<<cellDB, 256>>>(gatesD, dbih, dbhh, hDec, cDec, IDIM, TDIM * IDIM);
    for (int l = 1; l < LNUM; ++l) {
        gemm_nt<0><<<gridD, 256>>>(gatesD, enc, dWih + (size_t)l * GD * HENC, GD, HENC);
        gemm_nt<1><<<gridD, 256>>>(gatesD, hDec, dWhh + (size_t)l * GD * IDIM, GD, IDIM);
        cell_kernel<0><<<cellDB, 256>>>(gatesD, dbih + l * GD, dbhh + l * GD,
                                        hDec, cDec, IDIM, TDIM * IDIM);
    }

    lsm_kernel<<<(TDIM * 32 + 255) / 256, 256>>>(hDec, out);
}

// round 9
// speedup vs baseline: 1.0527x; 1.0527x over previous
#include <cuda_runtime.h>
#include <cstdint>
#include <math.h>
#include <mma.h>

using namespace nvcuda;

// True problem dims: T=4096, I=101, H=1000, L=4
#define TDIM 4096
#define IDIM 101
#define HENC 1000
#define LNUM 4
#define GE (4*HENC)   // 4000
#define GD (4*IDIM)   // 404
#define GDP 416       // padded decoder gate width (multiple of 16)

// ---------------- scratch (device globals; no allocation) ----------------
__device__ float g_gxE [(size_t)TDIM * (LNUM*GE)]; // 4096 x 16000: all enc x-projections
__device__ float g_gxD [(size_t)TDIM * (LNUM*GD)]; // 4096 x 1616 : all dec input projections
__device__ float g_gatesE[(size_t)TDIM * GE];      // per-layer enc h-projection
__device__ float g_gatesD[(size_t)TDIM * GDP];     // per-layer dec h-projection (padded)
__device__ float g_hEnc[(size_t)TDIM * HENC];
__device__ float g_cEnc[(size_t)TDIM * HENC];
__device__ float g_enc [(size_t)TDIM * HENC];
__device__ float g_hDec[(size_t)TDIM * IDIM];
__device__ float g_cDec[(size_t)TDIM * IDIM];

__device__ __forceinline__ float sigf(float x) { return 1.0f / (1.0f + expf(-x)); }

// ---------------- tf32 GEMM: C[M,Nc] = A[M,K] @ B[N,K]^T ----------------
// M multiple of 128. N = real rows of B (guarded). Nc = store width (mult of 16),
// ldc = row stride of C. Tiles fully beyond Nc are skipped (Nc % 16 == 0 ensures
// no partial 16-col tiles). 256 threads = 8 warps, warp tile 64x32.
#define BM 128
#define BN 128
#define BK 32

__global__ __launch_bounds__(256)
void gemm_tf32(float* __restrict__ C, const float* __restrict__ A,
               const float* __restrict__ B, int N, int K, int Nc, int ldc) {
    __shared__ __align__(16) float As[BM][BK + 4];
    __shared__ __align__(16) float Bs[BN][BK + 4];
    const int tid = threadIdx.x;
    const int m0 = blockIdx.y * BM;
    const int n0 = blockIdx.x * BN;
    const int wid = tid >> 5;
    const int wm = wid >> 2;          // 0..1
    const int wn = wid & 3;           // 0..3

    wmma::fragment<wmma::accumulator, 16, 16, 8, float> acc[4][2];
    #pragma unroll
    for (int i = 0; i < 4; ++i)
        #pragma unroll
        for (int j = 0; j < 2; ++j) wmma::fill_fragment(acc[i][j], 0.0f);

    for (int k0 = 0; k0 < K; k0 += BK) {
        // stage A(128x32) and B(128x32), guarded
        #pragma unroll
        for (int t = 0; t < 16; ++t) {
            int e = tid + t * 256;
            int m = e >> 5;           // 0..127
            int k = e & 31;
            int gk = k0 + k;
            As[m][k] = (gk < K) ? A[(size_t)(m0 + m) * K + gk] : 0.0f;
            Bs[m][k] = (gk < K && (n0 + m) < N) ? B[(size_t)(n0 + m) * K + gk] : 0.0f;
        }
        __syncthreads();

        #pragma unroll
        for (int ks = 0; ks < BK / 8; ++ks) {
            wmma::fragment<wmma::matrix_a, 16, 16, 8, wmma::precision::tf32, wmma::row_major> af[4];
            wmma::fragment<wmma::matrix_b, 16, 16, 8, wmma::precision::tf32, wmma::col_major> bf[2];
            #pragma unroll
            for (int i = 0; i < 4; ++i) {
                wmma::load_matrix_sync(af[i], &As[wm * 64 + i * 16][ks * 8], BK + 4);
                #pragma unroll
                for (int t = 0; t < af[i].num_elements; ++t)
                    af[i].x[t] = wmma::__float_to_tf32(af[i].x[t]);
            }
            #pragma unroll
            for (int j = 0; j < 2; ++j) {
                wmma::load_matrix_sync(bf[j], &Bs[wn * 32 + j * 16][ks * 8], BK + 4);
                #pragma unroll
                for (int t = 0; t < bf[j].num_elements; ++t)
                    bf[j].x[t] = wmma::__float_to_tf32(bf[j].x[t]);
            }
            #pragma unroll
            for (int i = 0; i < 4; ++i)
                #pragma unroll
                for (int j = 0; j < 2; ++j)
                    wmma::mma_sync(acc[i][j], af[i], bf[j], acc[i][j]);
        }
        __syncthreads();
    }

    #pragma unroll
    for (int i = 0; i < 4; ++i) {
        int row = m0 + wm * 64 + i * 16;
        #pragma unroll
        for (int j = 0; j < 2; ++j) {
            int col = n0 + wn * 32 + j * 16;
            if (col + 16 <= Nc)
                wmma::store_matrix_sync(&C[(size_t)row * ldc + col], acc[i][j],
                                        ldc, wmma::mem_row_major);
        }
    }
}

// ---------------- LSTM cell: gates = gx(+gh) + bih + bhh ----------------
template<int FIRST>   // FIRST: c starts at 0, no gh term
__global__ void cell_kernel(const float* __restrict__ gx, int gxs,
                            const float* __restrict__ gh, int ghs,
                            const float* __restrict__ bih,
                            const float* __restrict__ bhh,
                            float* __restrict__ h, float* __restrict__ c,
                            int H, int total) {
    int idx = blockIdx.x * blockDim.x + threadIdx.x;
    if (idx >= total) return;
    int m = idx / H, n = idx - m * H;
    const float* gr = gx + (size_t)m * gxs;
    float gi = gr[n]         + bih[n]         + bhh[n];
    float gf = gr[H + n]     + bih[H + n]     + bhh[H + n];
    float gg = gr[2 * H + n] + bih[2 * H + n] + bhh[2 * H + n];
    float go = gr[3 * H + n] + bih[3 * H + n] + bhh[3 * H + n];
    if (!FIRST) {
        const float* hr = gh + (size_t)m * ghs;
        gi += hr[n];
        gf += hr[H + n];
        gg += hr[2 * H + n];
        go += hr[3 * H + n];
    }
    float cc = FIRST ? 0.0f : c[idx];
    cc = sigf(gf) * cc + sigf(gi) * tanhf(gg);
    float hh = sigf(go) * tanhf(cc);
    c[idx] = cc;
    h[idx] = hh;
}

__global__ void relu_kernel(const float* __restrict__ in, float* __restrict__ o, int n) {
    int i = blockIdx.x * blockDim.x + threadIdx.x;
    if (i < n) o[i] = fmaxf(in[i], 0.0f);
}

// ---------------- log_softmax: warp per row over 101 cols ----------------
__global__ void lsm_kernel(const float* __restrict__ h, float* __restrict__ out) {
    int w = (blockIdx.x * blockDim.x + threadIdx.x) >> 5;
    int lane = threadIdx.x & 31;
    if (w >= TDIM) return;
    const float* r = h + (size_t)w * IDIM;
    float v[4];
    float m = -1e30f;
    #pragma unroll
    for (int it = 0; it < 4; ++it) {
        int n = lane + 32 * it;
        v[it] = (n < IDIM) ? r[n] : -1e30f;
        m = fmaxf(m, v[it]);
    }
    #pragma unroll
    for (int o = 16; o; o >>= 1) m = fmaxf(m, __shfl_xor_sync(0xffffffffu, m, o));
    float s = 0.0f;
    #pragma unroll
    for (int it = 0; it < 4; ++it) s += expf(v[it] - m);
    #pragma unroll
    for (int o = 16; o; o >>= 1) s += __shfl_xor_sync(0xffffffffu, s, o);
    float L = m + logf(s);
    #pragma unroll
    for (int it = 0; it < 4; ++it) {
        int n = lane + 32 * it;
        if (n < IDIM) out[(size_t)w * IDIM + n] = v[it] - L;
    }
}

extern "C" void kernel_launch(void* const* d_in, const int* in_sizes, int n_in,
                              void* d_out, int out_size) {
    // ---- Resolve inputs by element count ----
    // x=413,696 | enc_Wih=1,616,000* | enc_Whh=16,000,000 | enc_b=16,000 x2
    // dec_Wih=1,616,000* | dec_Whh=163,216 | dec_b=1,616 x2   (*collide -> adjacency)
    int ix = -1, ieWhh = -1, idWhh = -1;
    int iEB[2] = {0, 0}, nEB = 0;
    int iDB[2] = {0, 0}, nDB = 0;
    int iWI[2] = {0, 0}, nWI = 0;
    for (int i = 0; i < n_in; ++i) {
        const int s = in_sizes[i];
        if (s == 413696) ix = i;
        else if (s == 16000000) ieWhh = i;
        else if (s == 163216) idWhh = i;
        else if (s == 16000 && nEB < 2) iEB[nEB++] = i;
        else if (s == 1616 && nDB < 2) iDB[nDB++] = i;
        else if (s == 1616000 && nWI < 2) iWI[nWI++] = i;
    }
    bool a0e = (iWI[0] == ieWhh - 1) || (iWI[0] == ieWhh + 1);
    bool a1e = (iWI[1] == ieWhh - 1) || (iWI[1] == ieWhh + 1);
    bool a0d = (iWI[0] == idWhh - 1) || (iWI[0] == idWhh + 1);
    bool a1d = (iWI[1] == idWhh - 1) || (iWI[1] == idWhh + 1);
    int ieWih, idWih;
    if (a0e && !a1e)      { ieWih = iWI[0]; idWih = iWI[1]; }
    else if (a1e && !a0e) { ieWih = iWI[1]; idWih = iWI[0]; }
    else if (a0d && !a1d) { idWih = iWI[0]; ieWih = iWI[1]; }
    else if (a1d && !a0d) { idWih = iWI[1]; ieWih = iWI[0]; }
    else                  { ieWih = iWI[0]; idWih = iWI[1]; }
    if (ix < 0) ix = 0;
    if (ieWhh < 0) ieWhh = 0;
    if (idWhh < 0) idWhh = 0;

    const float* x    = (const float*)d_in[ix];
    const float* eWih = (const float*)d_in[ieWih];
    const float* eWhh = (const float*)d_in[ieWhh];
    const float* ebih = (const float*)d_in[iEB[0]];
    const float* ebhh = (const float*)d_in[iEB[1]];
    const float* dWih = (const float*)d_in[idWih];
    const float* dWhh = (const float*)d_in[idWhh];
    const float* dbih = (const float*)d_in[iDB[0]];
    const float* dbhh = (const float*)d_in[iDB[1]];
    float* out = (float*)d_out;

    float *gxE, *gxD, *gatesE, *gatesD, *hEnc, *cEnc, *enc, *hDec, *cDec;
    cudaGetSymbolAddress((void**)&gxE,    g_gxE);
    cudaGetSymbolAddress((void**)&gxD,    g_gxD);
    cudaGetSymbolAddress((void**)&gatesE, g_gatesE);
    cudaGetSymbolAddress((void**)&gatesD, g_gatesD);
    cudaGetSymbolAddress((void**)&hEnc,   g_hEnc);
    cudaGetSymbolAddress((void**)&cEnc,   g_cEnc);
    cudaGetSymbolAddress((void**)&enc,    g_enc);
    cudaGetSymbolAddress((void**)&hDec,   g_hDec);
    cudaGetSymbolAddress((void**)&cDec,   g_cDec);

    const int MB = TDIM / BM;                       // 32
    const int cellEB = (TDIM * HENC + 255) / 256;
    const int cellDB = (TDIM * IDIM + 255) / 256;

    // ---- All encoder x-projections in ONE GEMM: [4096,16000] = x @ eWih^T ----
    gemm_tf32<<<dim3(LNUM * GE / BN, MB), 256>>>(gxE, x, eWih,
                                                 LNUM * GE, IDIM, LNUM * GE, LNUM * GE);
    // ---- Encoder layers ----
    cell_kernel<1><<<cellEB, 256>>>(gxE, LNUM * GE, nullptr, 0,
                                    ebih, ebhh, hEnc, cEnc, HENC, TDIM * HENC);
    for (int l = 1; l < LNUM; ++l) {
        gemm_tf32<<<dim3((GE + BN - 1) / BN, MB), 256>>>(
            gatesE, hEnc, eWhh + (size_t)l * GE * HENC, GE, HENC, GE, GE);
        cell_kernel<0><<<cellEB, 256>>>(gxE + (size_t)l * GE, LNUM * GE, gatesE, GE,
                                        ebih + l * GE, ebhh + l * GE,
                                        hEnc, cEnc, HENC, TDIM * HENC);
    }
    relu_kernel<<<(TDIM * HENC + 255) / 256, 256>>>(hEnc, enc, TDIM * HENC);

    // ---- All decoder input projections in ONE GEMM: [4096,1616] = enc @ dWih^T ----
    gemm_tf32<<<dim3((LNUM * GD + BN - 1) / BN, MB), 256>>>(
        gxD, enc, dWih, LNUM * GD, HENC, LNUM * GD, LNUM * GD);
    // ---- Decoder layers ----
    cell_kernel<1><<<cellDB, 256>>>(gxD, LNUM * GD, nullptr, 0,
                                    dbih, dbhh, hDec, cDec, IDIM, TDIM * IDIM);
    for (int l = 1; l < LNUM; ++l) {
        gemm_tf32<<<dim3((GDP + BN - 1) / BN, MB), 256>>>(
            gatesD, hDec, dWhh + (size_t)l * GD * IDIM, GD, IDIM, GDP, GDP);
        cell_kernel<0><<<cellDB, 256>>>(gxD + (size_t)l * GD, LNUM * GD, gatesD, GDP,
                                        dbih + l * GD, dbhh + l * GD,
                                        hDec, cDec, IDIM, TDIM * IDIM);
    }

    lsm_kernel<<<(TDIM * 32 + 255) / 256, 256>>>(hDec, out);
}

// round 10
// speedup vs baseline: 3.7466x; 3.5589x over previous
#include <cuda_runtime.h>
#include <cuda_bf16.h>
#include <cstdint>
#include <math.h>
#include <mma.h>

using namespace nvcuda;
typedef __nv_bfloat16 bf16;

// True dims: T=4096, I=101, H=1000, L=4
#define TDIM 4096
#define IDIM 101
#define HENC 1000
#define LNUM 4
#define GE 4000      // 4*HENC
#define GD 404       // 4*IDIM
// Padded dims (N -> mult of 128, K -> mult of 32)
#define KX 128       // K for x / dec-h GEMMs (101 -> 128)
#define KH 1024      // K for henc GEMMs (1000 -> 1024)
#define NE 4096      // per-layer enc gate width (4000 -> 4096)
#define NGXE 16000   // all enc x-projections (4*4000, already mult 128)
#define NGXD 1664    // all dec input projections (4*404=1616 -> 1664)
#define ND 512       // per-layer dec gate width (404 -> 512)

// ---------------- scratch (device globals; no allocation) ----------------
__device__ float g_gxE   [(size_t)TDIM * NGXE];
__device__ float g_gatesE[(size_t)TDIM * NE];
__device__ float g_gxD   [(size_t)TDIM * NGXD];
__device__ float g_gatesD[(size_t)TDIM * ND];
__device__ float g_cEnc  [(size_t)TDIM * HENC];
__device__ float g_cDec  [(size_t)TDIM * IDIM];
__device__ float g_hDec  [(size_t)TDIM * IDIM];
__device__ __align__(16) bf16 g_xb   [(size_t)TDIM * KX];
__device__ __align__(16) bf16 g_eWihb[(size_t)NGXE * KX];
__device__ __align__(16) bf16 g_eWhhb[(size_t)LNUM * NE * KH];
__device__ __align__(16) bf16 g_dWihb[(size_t)NGXD * KH];
__device__ __align__(16) bf16 g_dWhhb[(size_t)LNUM * ND * KX];
__device__ __align__(16) bf16 g_hEncb[(size_t)TDIM * KH];
__device__ __align__(16) bf16 g_encb [(size_t)TDIM * KH];
__device__ __align__(16) bf16 g_hDecb[(size_t)TDIM * KX];

__device__ __forceinline__ float sigf(float x) { return 1.0f / (1.0f + expf(-x)); }

// ---------------- pad-convert fp32 -> bf16 (zero pads) ----------------
__global__ void cvt_pad(bf16* __restrict__ dst, const float* __restrict__ src,
                        int N, int K, int Np, int Kp) {
    int idx = blockIdx.x * blockDim.x + threadIdx.x;
    int tot = Np * Kp;
    if (idx >= tot) return;
    int n = idx / Kp, k = idx - n * Kp;
    float v = (n < N && k < K) ? src[(size_t)n * K + k] : 0.0f;
    dst[idx] = __float2bfloat16(v);
}

__global__ void zero_bf16(bf16* __restrict__ p, int n) {
    int i = blockIdx.x * blockDim.x + threadIdx.x;
    if (i < n) p[i] = __float2bfloat16(0.0f);
}

// ---------------- bf16 GEMM: C[M, ldc] = A[M,Kp] @ B[N,Kp]^T ----------------
// All dims padded: M mult 128, grid.x*128 = N (mult 128), Kp mult 32. No guards.
#define BM 128
#define BN 128
#define BK 32
#define LDS (BK + 8)   // 40 bf16 = 80B rows (16B-aligned chunks)

__device__ __forceinline__ void cp16(void* dst, const void* src) {
    uint32_t d = (uint32_t)__cvta_generic_to_shared(dst);
    asm volatile("cp.async.cg.shared.global [%0], [%1], 16;\n" :: "r"(d), "l"(src));
}

__global__ __launch_bounds__(256)
void gemm_bf16(float* __restrict__ C, const bf16* __restrict__ A,
               const bf16* __restrict__ B, int Kp, int ldc) {
    __shared__ __align__(16) bf16 As[2][BM][LDS];
    __shared__ __align__(16) bf16 Bs[2][BM][LDS];
    const int tid = threadIdx.x;
    const int m0 = blockIdx.y * BM;
    const int n0 = blockIdx.x * BN;
    const int wid = tid >> 5;
    const int wm = wid >> 2;      // 0..1 -> 64-row slab
    const int wn = wid & 3;       // 0..3 -> 32-col slab

    wmma::fragment<wmma::accumulator, 16, 16, 16, float> acc[4][2];
    #pragma unroll
    for (int i = 0; i < 4; ++i)
        #pragma unroll
        for (int j = 0; j < 2; ++j) wmma::fill_fragment(acc[i][j], 0.0f);

    const int r0 = tid >> 2;             // 0..63
    const int c0 = (tid & 3) * 8;        // 0,8,16,24

    auto stage = [&](int k0, int buf) {
        #pragma unroll
        for (int i = 0; i < 2; ++i) {
            int row = r0 + i * 64;
            cp16(&As[buf][row][c0], A + (size_t)(m0 + row) * Kp + k0 + c0);
            cp16(&Bs[buf][row][c0], B + (size_t)(n0 + row) * Kp + k0 + c0);
        }
        asm volatile("cp.async.commit_group;\n" ::);
    };

    stage(0, 0);
    const int nk = Kp / BK;
    for (int it = 0; it < nk; ++it) {
        if (it + 1 < nk) {
            stage((it + 1) * BK, (it + 1) & 1);
            asm volatile("cp.async.wait_group 1;\n" ::);
        } else {
            asm volatile("cp.async.wait_group 0;\n" ::);
        }
        __syncthreads();
        const int buf = it & 1;
        #pragma unroll
        for (int ks = 0; ks < 2; ++ks) {
            wmma::fragment<wmma::matrix_a, 16, 16, 16, bf16, wmma::row_major> af[4];
            wmma::fragment<wmma::matrix_b, 16, 16, 16, bf16, wmma::col_major> bfr[2];
            #pragma unroll
            for (int i = 0; i < 4; ++i)
                wmma::load_matrix_sync(af[i], &As[buf][wm * 64 + i * 16][ks * 16], LDS);
            #pragma unroll
            for (int j = 0; j < 2; ++j)
                wmma::load_matrix_sync(bfr[j], &Bs[buf][wn * 32 + j * 16][ks * 16], LDS);
            #pragma unroll
            for (int i = 0; i < 4; ++i)
                #pragma unroll
                for (int j = 0; j < 2; ++j)
                    wmma::mma_sync(acc[i][j], af[i], bfr[j], acc[i][j]);
        }
        __syncthreads();
    }

    #pragma unroll
    for (int i = 0; i < 4; ++i) {
        int row = m0 + wm * 64 + i * 16;
        #pragma unroll
        for (int j = 0; j < 2; ++j) {
            int col = n0 + wn * 32 + j * 16;
            wmma::store_matrix_sync(&C[(size_t)row * ldc + col], acc[i][j],
                                    ldc, wmma::mem_row_major);
        }
    }
}

// ---------------- LSTM cell ----------------
template<int FIRST, int WF32>
__global__ void cell_kernel(const float* __restrict__ gx, int gxs,
                            const float* __restrict__ gh, int ghs,
                            const float* __restrict__ bih,
                            const float* __restrict__ bhh,
                            float* __restrict__ h,
                            bf16* __restrict__ hb, int hbs,
                            float* __restrict__ c, int H, int total) {
    int idx = blockIdx.x * blockDim.x + threadIdx.x;
    if (idx >= total) return;
    int m = idx / H, n = idx - m * H;
    const float* gr = gx + (size_t)m * gxs;
    float gi = gr[n]         + bih[n]         + bhh[n];
    float gf = gr[H + n]     + bih[H + n]     + bhh[H + n];
    float gg = gr[2 * H + n] + bih[2 * H + n] + bhh[2 * H + n];
    float go = gr[3 * H + n] + bih[3 * H + n] + bhh[3 * H + n];
    if (!FIRST) {
        const float* hr = gh + (size_t)m * ghs;
        gi += hr[n];
        gf += hr[H + n];
        gg += hr[2 * H + n];
        go += hr[3 * H + n];
    }
    float cc = FIRST ? 0.0f : c[idx];
    cc = sigf(gf) * cc + sigf(gi) * tanhf(gg);
    float hh = sigf(go) * tanhf(cc);
    c[idx] = cc;
    if (WF32) h[idx] = hh;
    hb[(size_t)m * hbs + n] = __float2bfloat16(hh);
}

// relu over the full padded width (pads are zero; relu(0)=0)
__global__ void relu_bf16(const bf16* __restrict__ in, bf16* __restrict__ o, int n) {
    int i = blockIdx.x * blockDim.x + threadIdx.x;
    if (i < n) {
        float v = __bfloat162float(in[i]);
        o[i] = __float2bfloat16(fmaxf(v, 0.0f));
    }
}

// ---------------- log_softmax: warp per row ----------------
__global__ void lsm_kernel(const float* __restrict__ h, float* __restrict__ out) {
    int w = (blockIdx.x * blockDim.x + threadIdx.x) >> 5;
    int lane = threadIdx.x & 31;
    if (w >= TDIM) return;
    const float* r = h + (size_t)w * IDIM;
    float v[4];
    float m = -1e30f;
    #pragma unroll
    for (int it = 0; it < 4; ++it) {
        int n = lane + 32 * it;
        v[it] = (n < IDIM) ? r[n] : -1e30f;
        m = fmaxf(m, v[it]);
    }
    #pragma unroll
    for (int o = 16; o; o >>= 1) m = fmaxf(m, __shfl_xor_sync(0xffffffffu, m, o));
    float s = 0.0f;
    #pragma unroll
    for (int it = 0; it < 4; ++it) s += expf(v[it] - m);
    #pragma unroll
    for (int o = 16; o; o >>= 1) s += __shfl_xor_sync(0xffffffffu, s, o);
    float L = m + logf(s);
    #pragma unroll
    for (int it = 0; it < 4; ++it) {
        int n = lane + 32 * it;
        if (n < IDIM) out[(size_t)w * IDIM + n] = v[it] - L;
    }
}

extern "C" void kernel_launch(void* const* d_in, const int* in_sizes, int n_in,
                              void* d_out, int out_size) {
    // ---- Resolve inputs by element count ----
    int ix = -1, ieWhh = -1, idWhh = -1;
    int iEB[2] = {0, 0}, nEB = 0;
    int iDB[2] = {0, 0}, nDB = 0;
    int iWI[2] = {0, 0}, nWI = 0;
    for (int i = 0; i < n_in; ++i) {
        const int s = in_sizes[i];
        if (s == 413696) ix = i;
        else if (s == 16000000) ieWhh = i;
        else if (s == 163216) idWhh = i;
        else if (s == 16000 && nEB < 2) iEB[nEB++] = i;
        else if (s == 1616 && nDB < 2) iDB[nDB++] = i;
        else if (s == 1616000 && nWI < 2) iWI[nWI++] = i;
    }
    bool a0e = (iWI[0] == ieWhh - 1) || (iWI[0] == ieWhh + 1);
    bool a1e = (iWI[1] == ieWhh - 1) || (iWI[1] == ieWhh + 1);
    bool a0d = (iWI[0] == idWhh - 1) || (iWI[0] == idWhh + 1);
    bool a1d = (iWI[1] == idWhh - 1) || (iWI[1] == idWhh + 1);
    int ieWih, idWih;
    if (a0e && !a1e)      { ieWih = iWI[0]; idWih = iWI[1]; }
    else if (a1e && !a0e) { ieWih = iWI[1]; idWih = iWI[0]; }
    else if (a0d && !a1d) { idWih = iWI[0]; ieWih = iWI[1]; }
    else if (a1d && !a0d) { idWih = iWI[1]; ieWih = iWI[0]; }
    else                  { ieWih = iWI[0]; idWih = iWI[1]; }
    if (ix < 0) ix = 0;
    if (ieWhh < 0) ieWhh = 0;
    if (idWhh < 0) idWhh = 0;

    const float* x    = (const float*)d_in[ix];
    const float* eWih = (const float*)d_in[ieWih];
    const float* eWhh = (const float*)d_in[ieWhh];
    const float* ebih = (const float*)d_in[iEB[0]];
    const float* ebhh = (const float*)d_in[iEB[1]];
    const float* dWih = (const float*)d_in[idWih];
    const float* dWhh = (const float*)d_in[idWhh];
    const float* dbih = (const float*)d_in[iDB[0]];
    const float* dbhh = (const float*)d_in[iDB[1]];
    float* out = (float*)d_out;

    float *gxE, *gatesE, *gxD, *gatesD, *cEnc, *cDec, *hDec;
    bf16 *xb, *eWihb, *eWhhb, *dWihb, *dWhhb, *hEncb, *encb, *hDecb;
    cudaGetSymbolAddress((void**)&gxE,    g_gxE);
    cudaGetSymbolAddress((void**)&gatesE, g_gatesE);
    cudaGetSymbolAddress((void**)&gxD,    g_gxD);
    cudaGetSymbolAddress((void**)&gatesD, g_gatesD);
    cudaGetSymbolAddress((void**)&cEnc,   g_cEnc);
    cudaGetSymbolAddress((void**)&cDec,   g_cDec);
    cudaGetSymbolAddress((void**)&hDec,   g_hDec);
    cudaGetSymbolAddress((void**)&xb,     g_xb);
    cudaGetSymbolAddress((void**)&eWihb,  g_eWihb);
    cudaGetSymbolAddress((void**)&eWhhb,  g_eWhhb);
    cudaGetSymbolAddress((void**)&dWihb,  g_dWihb);
    cudaGetSymbolAddress((void**)&dWhhb,  g_dWhhb);
    cudaGetSymbolAddress((void**)&hEncb,  g_hEncb);
    cudaGetSymbolAddress((void**)&encb,   g_encb);
    cudaGetSymbolAddress((void**)&hDecb,  g_hDecb);

    #define GRID1(n) (((n) + 255) / 256), 256

    // ---- Convert weights/inputs to padded bf16 ----
    cvt_pad<<<GRID1(TDIM * KX)>>>(xb, x, TDIM, IDIM, TDIM, KX);
    cvt_pad<<<GRID1(NGXE * KX)>>>(eWihb, eWih, LNUM * GE, IDIM, NGXE, KX);
    for (int l = 0; l < LNUM; ++l)
        cvt_pad<<<GRID1(NE * KH)>>>(eWhhb + (size_t)l * NE * KH,
                                    eWhh + (size_t)l * GE * HENC, GE, HENC, NE, KH);
    cvt_pad<<<GRID1(NGXD * KH)>>>(dWihb, dWih, LNUM * GD, HENC, NGXD, KH);
    for (int l = 0; l < LNUM; ++l)
        cvt_pad<<<GRID1(ND * KX)>>>(dWhhb + (size_t)l * ND * KX,
                                    dWhh + (size_t)l * GD * IDIM, GD, IDIM, ND, KX);
    // zero activation pads (cells only write valid cols)
    zero_bf16<<<GRID1(TDIM * KH)>>>(hEncb, TDIM * KH);
    zero_bf16<<<GRID1(TDIM * KX)>>>(hDecb, TDIM * KX);

    const int MB = TDIM / BM;   // 32
    const int cellEB = (TDIM * HENC + 255) / 256;
    const int cellDB = (TDIM * IDIM + 255) / 256;

    // ---- Encoder ----
    gemm_bf16<<<dim3(NGXE / BN, MB), 256>>>(gxE, xb, eWihb, KX, NGXE);
    cell_kernel<1, 0><<<cellEB, 256>>>(gxE, NGXE, nullptr, 0, ebih, ebhh,
                                       nullptr, hEncb, KH, cEnc, HENC, TDIM * HENC);
    for (int l = 1; l < LNUM; ++l) {
        gemm_bf16<<<dim3(NE / BN, MB), 256>>>(gatesE, hEncb,
                                              eWhhb + (size_t)l * NE * KH, KH, NE);
        cell_kernel<0, 0><<<cellEB, 256>>>(gxE + (size_t)l * GE, NGXE, gatesE, NE,
                                           ebih + l * GE, ebhh + l * GE,
                                           nullptr, hEncb, KH, cEnc, HENC, TDIM * HENC);
    }
    relu_bf16<<<GRID1(TDIM * KH)>>>(hEncb, encb, TDIM * KH);

    // ---- Decoder ----
    gemm_bf16<<<dim3(NGXD / BN, MB), 256>>>(gxD, encb, dWihb, KH, NGXD);
    cell_kernel<1, 1><<<cellDB, 256>>>(gxD, NGXD, nullptr, 0, dbih, dbhh,
                                       hDec, hDecb, KX, cDec, IDIM, TDIM * IDIM);
    for (int l = 1; l < LNUM; ++l) {
        gemm_bf16<<<dim3(ND / BN, MB), 256>>>(gatesD, hDecb,
                                              dWhhb + (size_t)l * ND * KX, KX, ND);
        cell_kernel<0, 1><<<cellDB, 256>>>(gxD + (size_t)l * GD, NGXD, gatesD, ND,
                                           dbih + l * GD, dbhh + l * GD,
                                           hDec, hDecb, KX, cDec, IDIM, TDIM * IDIM);
    }

    lsm_kernel<<<(TDIM * 32 + 255) / 256, 256>>>(hDec, out);
}

// round 12
// speedup vs baseline: 3.7824x; 1.0096x over previous
#include <cuda_runtime.h>
#include <cuda_bf16.h>
#include <cuda_fp16.h>
#include <cstdint>
#include <math.h>
#include <mma.h>

using namespace nvcuda;
typedef __nv_bfloat16 bf16;

// True dims: T=4096, I=101, H=1000, L=4
#define TDIM 4096
#define IDIM 101
#define HENC 1000
#define LNUM 4
#define GE 4000
#define GD 404
// Padded: K -> mult 64, N -> mult 256
#define KX 128
#define KH 1024
#define NE 4096      // per-layer enc gate width (4000 -> 4096)
#define NGXE 16128   // all enc x-projections (16000 -> 16128, mult 256)
#define NGXD 1792    // all dec input projections (1616 -> 1792)
#define ND 512       // per-layer dec gate width

// ---------------- scratch (device globals; no allocation) ----------------
__device__ __half g_gxE   [(size_t)TDIM * NGXE];
__device__ __half g_gatesE[(size_t)TDIM * NE];
__device__ __half g_gxD   [(size_t)TDIM * NGXD];
__device__ __half g_gatesD[(size_t)TDIM * ND];
__device__ float  g_cEnc  [(size_t)TDIM * HENC];
__device__ float  g_cDec  [(size_t)TDIM * IDIM];
__device__ float  g_hDec  [(size_t)TDIM * IDIM];
__device__ __align__(16) bf16 g_xb   [(size_t)TDIM * KX];
__device__ __align__(16) bf16 g_eWihb[(size_t)NGXE * KX];
__device__ __align__(16) bf16 g_eWhhb[(size_t)LNUM * NE * KH];
__device__ __align__(16) bf16 g_dWihb[(size_t)NGXD * KH];
__device__ __align__(16) bf16 g_dWhhb[(size_t)LNUM * ND * KX];
__device__ __align__(16) bf16 g_hEncb[(size_t)TDIM * KH];
__device__ __align__(16) bf16 g_encb [(size_t)TDIM * KH];
__device__ __align__(16) bf16 g_hDecb[(size_t)TDIM * KX];

__device__ __forceinline__ float sigf(float x) { return 1.0f / (1.0f + expf(-x)); }

// ---------------- bf16 GEMM: C_f16[M, ldc] = A[M,Kp] @ B[N,Kp]^T ----------------
// CTA tile 128x256, warp tile 64x64 (8 warps), BK=64, 3-stage cp.async ring.
// All dims padded (M mult 128, grid.x*256 = Np, Kp mult 64). No guards.
#define BM 128
#define BN 256
#define BK 64
#define NSTG 3
#define LDA 72                       // 64 + 8 pad (144B rows, 16B aligned)
#define STG_A (BM * LDA * 2)         // 18432
#define STG_B (BN * LDA * 2)         // 36864
#define STG_SZ (STG_A + STG_B)       // 55296
#define SM_TOTAL (NSTG * STG_SZ)     // 165888
#define LDC_S 264                    // f32 epilogue smem stride (mult 8)

__device__ __forceinline__ void cp16(void* dst, const void* src) {
    uint32_t d = (uint32_t)__cvta_generic_to_shared(dst);
    asm volatile("cp.async.cg.shared.global [%0], [%1], 16;" :: "r"(d), "l"(src));
}

__global__ __launch_bounds__(256)
void gemm_bf16(__half* __restrict__ C, const bf16* __restrict__ A,
               const bf16* __restrict__ B, int Kp, int ldc) {
    extern __shared__ __align__(16) char smem[];
    const int tid = threadIdx.x;
    const int wid = tid >> 5;
    const int wm = wid >> 2;      // 0..1 -> 64-row slab
    const int wn = wid & 3;       // 0..3 -> 64-col slab
    const int m0 = blockIdx.y * BM;
    const int n0 = blockIdx.x * BN;
    const int nk = Kp / BK;

    wmma::fragment<wmma::accumulator, 16, 16, 16, float> acc[4][4];
    #pragma unroll
    for (int i = 0; i < 4; ++i)
        #pragma unroll
        for (int j = 0; j < 4; ++j) wmma::fill_fragment(acc[i][j], 0.0f);

    auto stage = [&](int ck) {
        char* base = smem + (ck % NSTG) * STG_SZ;
        const bf16* Ag = A + (size_t)m0 * Kp + ck * BK;
        const bf16* Bg = B + (size_t)n0 * Kp + ck * BK;
        #pragma unroll
        for (int i = 0; i < 4; ++i) {           // A: 128 rows x 8 chunks
            int id = tid + i * 256;
            int r = id >> 3, c = id & 7;
            cp16(base + r * 144 + c * 16, Ag + (size_t)r * Kp + c * 8);
        }
        #pragma unroll
        for (int i = 0; i < 8; ++i) {           // B: 256 rows x 8 chunks
            int id = tid + i * 256;
            int r = id >> 3, c = id & 7;
            cp16(base + STG_A + r * 144 + c * 16, Bg + (size_t)r * Kp + c * 8);
        }
        asm volatile("cp.async.commit_group;" ::: "memory");
    };

    stage(0);
    if (nk > 1) stage(1);

    for (int it = 0; it < nk; ++it) {
        if (it < nk - 1) asm volatile("cp.async.wait_group 1;" ::: "memory");
        else             asm volatile("cp.async.wait_group 0;" ::: "memory");
        __syncthreads();
        if (it + 2 < nk) stage(it + 2);

        const bf16* As = (const bf16*)(smem + (it % NSTG) * STG_SZ);
        const bf16* Bs = (const bf16*)(smem + (it % NSTG) * STG_SZ + STG_A);
        #pragma unroll
        for (int ks = 0; ks < BK / 16; ++ks) {
            wmma::fragment<wmma::matrix_a, 16, 16, 16, bf16, wmma::row_major> af[4];
            wmma::fragment<wmma::matrix_b, 16, 16, 16, bf16, wmma::col_major> bfr[4];
            #pragma unroll
            for (int i = 0; i < 4; ++i)
                wmma::load_matrix_sync(af[i], As + (wm * 64 + i * 16) * LDA + ks * 16, LDA);
            #pragma unroll
            for (int j = 0; j < 4; ++j)
                wmma::load_matrix_sync(bfr[j], Bs + (wn * 64 + j * 16) * LDA + ks * 16, LDA);
            #pragma unroll
            for (int i = 0; i < 4; ++i)
                #pragma unroll
                for (int j = 0; j < 4; ++j)
                    wmma::mma_sync(acc[i][j], af[i], bfr[j], acc[i][j]);
        }
    }

    // ---- epilogue: f32 tile through smem -> fp16 global ----
    __syncthreads();
    float* Cs = (float*)smem;                 // 128 x 264 f32 = 135168 B <= SM_TOTAL
    #pragma unroll
    for (int i = 0; i < 4; ++i)
        #pragma unroll
        for (int j = 0; j < 4; ++j)
            wmma::store_matrix_sync(Cs + (size_t)(wm * 64 + i * 16) * LDC_S + wn * 64 + j * 16,
                                    acc[i][j], LDC_S, wmma::mem_row_major);
    __syncthreads();
    for (int id = tid; id < BM * (BN / 8); id += 256) {   // 8 halves per chunk
        int r = id / (BN / 8);
        int c = (id - r * (BN / 8)) * 8;
        const float* src = Cs + (size_t)r * LDC_S + c;
        __half2 h0 = __floats2half2_rn(src[0], src[1]);
        __half2 h1 = __floats2half2_rn(src[2], src[3]);
        __half2 h2 = __floats2half2_rn(src[4], src[5]);
        __half2 h3 = __floats2half2_rn(src[6], src[7]);
        uint4 v;
        v.x = *(uint32_t*)&h0; v.y = *(uint32_t*)&h1;
        v.z = *(uint32_t*)&h2; v.w = *(uint32_t*)&h3;
        *(uint4*)(C + (size_t)(m0 + r) * ldc + n0 + c) = v;
    }
}

// ---------------- pad-convert fp32 -> bf16 (zero pads) ----------------
__global__ void cvt_pad(bf16* __restrict__ dst, const float* __restrict__ src,
                        int N, int K, int Np, int Kp) {
    int idx = blockIdx.x * blockDim.x + threadIdx.x;
    if (idx >= Np * Kp) return;
    int n = idx / Kp, k = idx - n * Kp;
    float v = (n < N && k < K) ? src[(size_t)n * K + k] : 0.0f;
    dst[idx] = __float2bfloat16(v);
}

__global__ void zero_bf16(bf16* __restrict__ p, int n) {
    int i = blockIdx.x * blockDim.x + threadIdx.x;
    if (i < n) p[i] = __float2bfloat16(0.0f);
}

// ---------------- LSTM cell (fp16 gate inputs) ----------------
template<int FIRST, int WF32>
__global__ void cell_kernel(const __half* __restrict__ gx, int gxs,
                            const __half* __restrict__ gh, int ghs,
                            const float* __restrict__ bih,
                            const float* __restrict__ bhh,
                            float* __restrict__ h,
                            bf16* __restrict__ hb, int hbs,
                            float* __restrict__ c, int H, int total) {
    int idx = blockIdx.x * blockDim.x + threadIdx.x;
    if (idx >= total) return;
    int m = idx / H, n = idx - m * H;
    const __half* gr = gx + (size_t)m * gxs;
    float gi = __half2float(gr[n])         + bih[n]         + bhh[n];
    float gf = __half2float(gr[H + n])     + bih[H + n]     + bhh[H + n];
    float gg = __half2float(gr[2 * H + n]) + bih[2 * H + n] + bhh[2 * H + n];
    float go = __half2float(gr[3 * H + n]) + bih[3 * H + n] + bhh[3 * H + n];
    if (!FIRST) {
        const __half* hr = gh + (size_t)m * ghs;
        gi += __half2float(hr[n]);
        gf += __half2float(hr[H + n]);
        gg += __half2float(hr[2 * H + n]);
        go += __half2float(hr[3 * H + n]);
    }
    float cc = FIRST ? 0.0f : c[idx];
    cc = sigf(gf) * cc + sigf(gi) * tanhf(gg);
    float hh = sigf(go) * tanhf(cc);
    c[idx] = cc;
    if (WF32) h[idx] = hh;
    hb[(size_t)m * hbs + n] = __float2bfloat16(hh);
}

__global__ void relu_bf16(const bf16* __restrict__ in, bf16* __restrict__ o, int n) {
    int i = blockIdx.x * blockDim.x + threadIdx.x;
    if (i < n) {
        float v = __bfloat162float(in[i]);
        o[i] = __float2bfloat16(fmaxf(v, 0.0f));
    }
}

// ---------------- log_softmax ----------------
__global__ void lsm_kernel(const float* __restrict__ h, float* __restrict__ out) {
    int w = (blockIdx.x * blockDim.x + threadIdx.x) >> 5;
    int lane = threadIdx.x & 31;
    if (w >= TDIM) return;
    const float* r = h + (size_t)w * IDIM;
    float v[4];
    float m = -1e30f;
    #pragma unroll
    for (int it = 0; it < 4; ++it) {
        int n = lane + 32 * it;
        v[it] = (n < IDIM) ? r[n] : -1e30f;
        m = fmaxf(m, v[it]);
    }
    #pragma unroll
    for (int o = 16; o; o >>= 1) m = fmaxf(m, __shfl_xor_sync(0xffffffffu, m, o));
    float s = 0.0f;
    #pragma unroll
    for (int it = 0; it < 4; ++it) s += expf(v[it] - m);
    #pragma unroll
    for (int o = 16; o; o >>= 1) s += __shfl_xor_sync(0xffffffffu, s, o);
    float L = m + logf(s);
    #pragma unroll
    for (int it = 0; it < 4; ++it) {
        int n = lane + 32 * it;
        if (n < IDIM) out[(size_t)w * IDIM + n] = v[it] - L;
    }
}

extern "C" void kernel_launch(void* const* d_in, const int* in_sizes, int n_in,
                              void* d_out, int out_size) {
    // ---- Resolve inputs by element count (proven mapping) ----
    int ix = -1, ieWhh = -1, idWhh = -1;
    int iEB[2] = {0, 0}, nEB = 0;
    int iDB[2] = {0, 0}, nDB = 0;
    int iWI[2] = {0, 0}, nWI = 0;
    for (int i = 0; i < n_in; ++i) {
        const int s = in_sizes[i];
        if (s == 413696) ix = i;
        else if (s == 16000000) ieWhh = i;
        else if (s == 163216) idWhh = i;
        else if (s == 16000 && nEB < 2) iEB[nEB++] = i;
        else if (s == 1616 && nDB < 2) iDB[nDB++] = i;
        else if (s == 1616000 && nWI < 2) iWI[nWI++] = i;
    }
    bool a0e = (iWI[0] == ieWhh - 1) || (iWI[0] == ieWhh + 1);
    bool a1e = (iWI[1] == ieWhh - 1) || (iWI[1] == ieWhh + 1);
    bool a0d = (iWI[0] == idWhh - 1) || (iWI[0] == idWhh + 1);
    bool a1d = (iWI[1] == idWhh - 1) || (iWI[1] == idWhh + 1);
    int ieWih, idWih;
    if (a0e && !a1e)      { ieWih = iWI[0]; idWih = iWI[1]; }
    else if (a1e && !a0e) { ieWih = iWI[1]; idWih = iWI[0]; }
    else if (a0d && !a1d) { idWih = iWI[0]; ieWih = iWI[1]; }
    else if (a1d && !a0d) { idWih = iWI[1]; ieWih = iWI[0]; }
    else                  { ieWih = iWI[0]; idWih = iWI[1]; }
    if (ix < 0) ix = 0;
    if (ieWhh < 0) ieWhh = 0;
    if (idWhh < 0) idWhh = 0;

    const float* x    = (const float*)d_in[ix];
    const float* eWih = (const float*)d_in[ieWih];
    const float* eWhh = (const float*)d_in[ieWhh];
    const float* ebih = (const float*)d_in[iEB[0]];
    const float* ebhh = (const float*)d_in[iEB[1]];
    const float* dWih = (const float*)d_in[idWih];
    const float* dWhh = (const float*)d_in[idWhh];
    const float* dbih = (const float*)d_in[iDB[0]];
    const float* dbhh = (const float*)d_in[iDB[1]];
    float* out = (float*)d_out;

    __half *gxE, *gatesE, *gxD, *gatesD;
    float *cEnc, *cDec, *hDec;
    bf16 *xb, *eWihb, *eWhhb, *dWihb, *dWhhb, *hEncb, *encb, *hDecb;
    cudaGetSymbolAddress((void**)&gxE,    g_gxE);
    cudaGetSymbolAddress((void**)&gatesE, g_gatesE);
    cudaGetSymbolAddress((void**)&gxD,    g_gxD);
    cudaGetSymbolAddress((void**)&gatesD, g_gatesD);
    cudaGetSymbolAddress((void**)&cEnc,   g_cEnc);
    cudaGetSymbolAddress((void**)&cDec,   g_cDec);
    cudaGetSymbolAddress((void**)&hDec,   g_hDec);
    cudaGetSymbolAddress((void**)&xb,     g_xb);
    cudaGetSymbolAddress((void**)&eWihb,  g_eWihb);
    cudaGetSymbolAddress((void**)&eWhhb,  g_eWhhb);
    cudaGetSymbolAddress((void**)&dWihb,  g_dWihb);
    cudaGetSymbolAddress((void**)&dWhhb,  g_dWhhb);
    cudaGetSymbolAddress((void**)&hEncb,  g_hEncb);
    cudaGetSymbolAddress((void**)&encb,   g_encb);
    cudaGetSymbolAddress((void**)&hDecb,  g_hDecb);

    cudaFuncSetAttribute(gemm_bf16, cudaFuncAttributeMaxDynamicSharedMemorySize, SM_TOTAL);

    #define GRID1(n) (((n) + 255) / 256), 256

    // ---- Convert weights/inputs to padded bf16 ----
    cvt_pad<<<GRID1(TDIM * KX)>>>(xb, x, TDIM, IDIM, TDIM, KX);
    cvt_pad<<<GRID1(NGXE * KX)>>>(eWihb, eWih, LNUM * GE, IDIM, NGXE, KX);
    for (int l = 0; l < LNUM; ++l)
        cvt_pad<<<GRID1(NE * KH)>>>(eWhhb + (size_t)l * NE * KH,
                                    eWhh + (size_t)l * GE * HENC, GE, HENC, NE, KH);
    cvt_pad<<<GRID1(NGXD * KH)>>>(dWihb, dWih, LNUM * GD, HENC, NGXD, KH);
    for (int l = 0; l < LNUM; ++l)
        cvt_pad<<<GRID1(ND * KX)>>>(dWhhb + (size_t)l * ND * KX,
                                    dWhh + (size_t)l * GD * IDIM, GD, IDIM, ND, KX);
    zero_bf16<<<GRID1(TDIM * KH)>>>(hEncb, TDIM * KH);
    zero_bf16<<<GRID1(TDIM * KX)>>>(hDecb, TDIM * KX);

    const int MB = TDIM / BM;   // 32
    const int cellEB = (TDIM * HENC + 255) / 256;
    const int cellDB = (TDIM * IDIM + 255) / 256;

    // ---- Encoder ----
    gemm_bf16<<<dim3(NGXE / BN, MB), 256, SM_TOTAL>>>(gxE, xb, eWihb, KX, NGXE);
    cell_kernel<1, 0><<<cellEB, 256>>>(gxE, NGXE, nullptr, 0, ebih, ebhh,
                                       nullptr, hEncb, KH, cEnc, HENC, TDIM * HENC);
    for (int l = 1; l < LNUM; ++l) {
        gemm_bf16<<<dim3(NE / BN, MB), 256, SM_TOTAL>>>(gatesE, hEncb,
                                                        eWhhb + (size_t)l * NE * KH, KH, NE);
        cell_kernel<0, 0><<<cellEB, 256>>>(gxE + (size_t)l * GE, NGXE, gatesE, NE,
                                           ebih + l * GE, ebhh + l * GE,
                                           nullptr, hEncb, KH, cEnc, HENC, TDIM * HENC);
    }
    relu_bf16<<<GRID1(TDIM * KH)>>>(hEncb, encb, TDIM * KH);

    // ---- Decoder ----
    gemm_bf16<<<dim3(NGXD / BN, MB), 256, SM_TOTAL>>>(gxD, encb, dWihb, KH, NGXD);
    cell_kernel<1, 1><<<cellDB, 256>>>(gxD, NGXD, nullptr, 0, dbih, dbhh,
                                       hDec, hDecb, KX, cDec, IDIM, TDIM * IDIM);
    for (int l = 1; l < LNUM; ++l) {
        gemm_bf16<<<dim3(ND / BN, MB), 256, SM_TOTAL>>>(gatesD, hDecb,
                                                        dWhhb + (size_t)l * ND * KX, KX, ND);
        cell_kernel<0, 1><<<cellDB, 256>>>(gxD + (size_t)l * GD, NGXD, gatesD, ND,
                                           dbih + l * GD, dbhh + l * GD,
                                           hDec, hDecb, KX, cDec, IDIM, TDIM * IDIM);
    }

    lsm_kernel<<<(TDIM * 32 + 255) / 256, 256>>>(hDec, out);
}

// round 13
// speedup vs baseline: 3.8478x; 1.0173x over previous
#include <cuda_runtime.h>
#include <cuda_bf16.h>
#include <cuda_fp16.h>
#include <cstdint>
#include <math.h>
#include <mma.h>

using namespace nvcuda;
typedef __nv_bfloat16 bf16;

// True dims: T=4096, I=101, H=1000, L=4
#define TDIM 4096
#define IDIM 101
#define HENC 1000
#define LNUM 4
#define GE 4000
#define GD 404
// Padded: K -> mult 64, N -> mult 256
#define KX 128
#define KH 1024
#define NE 4096      // per-layer enc gate width (4000 -> 4096)
#define NGXE 16128   // all enc x-projections (16000 -> 16128)
#define NGXD 1792    // all dec input projections (1616 -> 1792)
#define ND 512       // per-layer dec gate width

// ---------------- scratch (device globals; no allocation) ----------------
__device__ __half g_gxE   [(size_t)TDIM * NGXE];
__device__ __half g_gatesE[(size_t)TDIM * NE];
__device__ __half g_gxD   [(size_t)TDIM * NGXD];
__device__ __half g_gatesD[(size_t)TDIM * ND];
__device__ float  g_cEnc  [(size_t)TDIM * HENC];
__device__ float  g_cDec  [(size_t)TDIM * IDIM];
__device__ float  g_hDec  [(size_t)TDIM * IDIM];
__device__ __align__(16) bf16 g_xb   [(size_t)TDIM * KX];
__device__ __align__(16) bf16 g_eWihb[(size_t)NGXE * KX];
__device__ __align__(16) bf16 g_eWhhb[(size_t)LNUM * NE * KH];
__device__ __align__(16) bf16 g_dWihb[(size_t)NGXD * KH];
__device__ __align__(16) bf16 g_dWhhb[(size_t)LNUM * ND * KX];
__device__ __align__(16) bf16 g_hEncb[(size_t)TDIM * KH];
__device__ __align__(16) bf16 g_encb [(size_t)TDIM * KH];
__device__ __align__(16) bf16 g_hDecb[(size_t)TDIM * KX];

__device__ __forceinline__ float sigf(float x) { return 1.0f / (1.0f + expf(-x)); }

// ---------------- bf16 GEMM (unchanged from passing R12) ----------------
#define BM 128
#define BN 256
#define BK 64
#define NSTG 3
#define LDA 72
#define STG_A (BM * LDA * 2)
#define STG_B (BN * LDA * 2)
#define STG_SZ (STG_A + STG_B)
#define SM_TOTAL (NSTG * STG_SZ)     // 165888
#define LDC_S 264

__device__ __forceinline__ void cp16(void* dst, const void* src) {
    uint32_t d = (uint32_t)__cvta_generic_to_shared(dst);
    asm volatile("cp.async.cg.shared.global [%0], [%1], 16;" :: "r"(d), "l"(src));
}

__global__ __launch_bounds__(256)
void gemm_bf16(__half* __restrict__ C, const bf16* __restrict__ A,
               const bf16* __restrict__ B, int Kp, int ldc) {
    extern __shared__ __align__(16) char smem[];
    const int tid = threadIdx.x;
    const int wid = tid >> 5;
    const int wm = wid >> 2;
    const int wn = wid & 3;
    const int m0 = blockIdx.y * BM;
    const int n0 = blockIdx.x * BN;
    const int nk = Kp / BK;

    wmma::fragment<wmma::accumulator, 16, 16, 16, float> acc[4][4];
    #pragma unroll
    for (int i = 0; i < 4; ++i)
        #pragma unroll
        for (int j = 0; j < 4; ++j) wmma::fill_fragment(acc[i][j], 0.0f);

    auto stage = [&](int ck) {
        char* base = smem + (ck % NSTG) * STG_SZ;
        const bf16* Ag = A + (size_t)m0 * Kp + ck * BK;
        const bf16* Bg = B + (size_t)n0 * Kp + ck * BK;
        #pragma unroll
        for (int i = 0; i < 4; ++i) {
            int id = tid + i * 256;
            int r = id >> 3, c = id & 7;
            cp16(base + r * 144 + c * 16, Ag + (size_t)r * Kp + c * 8);
        }
        #pragma unroll
        for (int i = 0; i < 8; ++i) {
            int id = tid + i * 256;
            int r = id >> 3, c = id & 7;
            cp16(base + STG_A + r * 144 + c * 16, Bg + (size_t)r * Kp + c * 8);
        }
        asm volatile("cp.async.commit_group;" ::: "memory");
    };

    stage(0);
    if (nk > 1) stage(1);

    for (int it = 0; it < nk; ++it) {
        if (it < nk - 1) asm volatile("cp.async.wait_group 1;" ::: "memory");
        else             asm volatile("cp.async.wait_group 0;" ::: "memory");
        __syncthreads();
        if (it + 2 < nk) stage(it + 2);

        const bf16* As = (const bf16*)(smem + (it % NSTG) * STG_SZ);
        const bf16* Bs = (const bf16*)(smem + (it % NSTG) * STG_SZ + STG_A);
        #pragma unroll
        for (int ks = 0; ks < BK / 16; ++ks) {
            wmma::fragment<wmma::matrix_a, 16, 16, 16, bf16, wmma::row_major> af[4];
            wmma::fragment<wmma::matrix_b, 16, 16, 16, bf16, wmma::col_major> bfr[4];
            #pragma unroll
            for (int i = 0; i < 4; ++i)
                wmma::load_matrix_sync(af[i], As + (wm * 64 + i * 16) * LDA + ks * 16, LDA);
            #pragma unroll
            for (int j = 0; j < 4; ++j)
                wmma::load_matrix_sync(bfr[j], Bs + (wn * 64 + j * 16) * LDA + ks * 16, LDA);
            #pragma unroll
            for (int i = 0; i < 4; ++i)
                #pragma unroll
                for (int j = 0; j < 4; ++j)
                    wmma::mma_sync(acc[i][j], af[i], bfr[j], acc[i][j]);
        }
    }

    __syncthreads();
    float* Cs = (float*)smem;
    #pragma unroll
    for (int i = 0; i < 4; ++i)
        #pragma unroll
        for (int j = 0; j < 4; ++j)
            wmma::store_matrix_sync(Cs + (size_t)(wm * 64 + i * 16) * LDC_S + wn * 64 + j * 16,
                                    acc[i][j], LDC_S, wmma::mem_row_major);
    __syncthreads();
    for (int id = tid; id < BM * (BN / 8); id += 256) {
        int r = id / (BN / 8);
        int c = (id - r * (BN / 8)) * 8;
        const float* src = Cs + (size_t)r * LDC_S + c;
        __half2 h0 = __floats2half2_rn(src[0], src[1]);
        __half2 h1 = __floats2half2_rn(src[2], src[3]);
        __half2 h2 = __floats2half2_rn(src[4], src[5]);
        __half2 h3 = __floats2half2_rn(src[6], src[7]);
        uint4 v;
        v.x = *(uint32_t*)&h0; v.y = *(uint32_t*)&h1;
        v.z = *(uint32_t*)&h2; v.w = *(uint32_t*)&h3;
        *(uint4*)(C + (size_t)(m0 + r) * ldc + n0 + c) = v;
    }
}

// ---------------- ONE mega convert/zero kernel (single launch) ----------------
#define SEG0 ((long long)TDIM * KX)          // xb
#define SEG1 ((long long)NGXE * KX)          // eWihb
#define SEG2 ((long long)LNUM * NE * KH)     // eWhhb
#define SEG3 ((long long)NGXD * KH)          // dWihb
#define SEG4 ((long long)LNUM * ND * KX)     // dWhhb
#define SEG5 ((long long)TDIM * KH)          // zero hEncb
#define SEG6 ((long long)TDIM * KH)          // zero encb (pads; cells fill valid part)
#define SEG7 ((long long)TDIM * KX)          // zero hDecb
#define SEG_TOT (SEG0+SEG1+SEG2+SEG3+SEG4+SEG5+SEG6+SEG7)

__global__ void megacvt(const float* __restrict__ x,
                        const float* __restrict__ eWih, const float* __restrict__ eWhh,
                        const float* __restrict__ dWih, const float* __restrict__ dWhh,
                        bf16* __restrict__ xb, bf16* __restrict__ eWihb,
                        bf16* __restrict__ eWhhb, bf16* __restrict__ dWihb,
                        bf16* __restrict__ dWhhb, bf16* __restrict__ hEncb,
                        bf16* __restrict__ encb, bf16* __restrict__ hDecb) {
    long long idx = (long long)blockIdx.x * blockDim.x + threadIdx.x;
    if (idx < SEG0) {
        int n = (int)(idx / KX), k = (int)(idx % KX);
        xb[idx] = __float2bfloat16(k < IDIM ? x[(size_t)n * IDIM + k] : 0.0f);
        return;
    }
    idx -= SEG0;
    if (idx < SEG1) {
        int n = (int)(idx / KX), k = (int)(idx % KX);
        float v = (n < LNUM * GE && k < IDIM) ? eWih[(size_t)n * IDIM + k] : 0.0f;
        eWihb[idx] = __float2bfloat16(v);
        return;
    }
    idx -= SEG1;
    if (idx < SEG2) {
        long long per = (long long)NE * KH;
        int l = (int)(idx / per);
        long long r = idx - (long long)l * per;
        int n = (int)(r / KH), k = (int)(r % KH);
        float v = (n < GE && k < HENC)
                ? eWhh[(size_t)l * GE * HENC + (size_t)n * HENC + k] : 0.0f;
        eWhhb[idx] = __float2bfloat16(v);
        return;
    }
    idx -= SEG2;
    if (idx < SEG3) {
        int n = (int)(idx / KH), k = (int)(idx % KH);
        float v = (n < LNUM * GD && k < HENC) ? dWih[(size_t)n * HENC + k] : 0.0f;
        dWihb[idx] = __float2bfloat16(v);
        return;
    }
    idx -= SEG3;
    if (idx < SEG4) {
        long long per = (long long)ND * KX;
        int l = (int)(idx / per);
        long long r = idx - (long long)l * per;
        int n = (int)(r / KX), k = (int)(r % KX);
        float v = (n < GD && k < IDIM)
                ? dWhh[(size_t)l * GD * IDIM + (size_t)n * IDIM + k] : 0.0f;
        dWhhb[idx] = __float2bfloat16(v);
        return;
    }
    idx -= SEG4;
    if (idx < SEG5) { hEncb[idx] = __float2bfloat16(0.0f); return; }
    idx -= SEG5;
    if (idx < SEG6) { encb[idx] = __float2bfloat16(0.0f); return; }
    idx -= SEG6;
    if (idx < SEG7) { hDecb[idx] = __float2bfloat16(0.0f); }
}

// ---------------- LSTM cell (fp16 gates; optional fused relu on hb) ----------------
template<int FIRST, int WF32, int RELU>
__global__ void cell_kernel(const __half* __restrict__ gx, int gxs,
                            const __half* __restrict__ gh, int ghs,
                            const float* __restrict__ bih,
                            const float* __restrict__ bhh,
                            float* __restrict__ h,
                            bf16* __restrict__ hb, int hbs,
                            float* __restrict__ c, int H, int total) {
    int idx = blockIdx.x * blockDim.x + threadIdx.x;
    if (idx >= total) return;
    int m = idx / H, n = idx - m * H;
    const __half* gr = gx + (size_t)m * gxs;
    float gi = __half2float(gr[n])         + bih[n]         + bhh[n];
    float gf = __half2float(gr[H + n])     + bih[H + n]     + bhh[H + n];
    float gg = __half2float(gr[2 * H + n]) + bih[2 * H + n] + bhh[2 * H + n];
    float go = __half2float(gr[3 * H + n]) + bih[3 * H + n] + bhh[3 * H + n];
    if (!FIRST) {
        const __half* hr = gh + (size_t)m * ghs;
        gi += __half2float(hr[n]);
        gf += __half2float(hr[H + n]);
        gg += __half2float(hr[2 * H + n]);
        go += __half2float(hr[3 * H + n]);
    }
    float cc = FIRST ? 0.0f : c[idx];
    cc = sigf(gf) * cc + sigf(gi) * tanhf(gg);
    float hh = sigf(go) * tanhf(cc);
    c[idx] = cc;
    if (WF32) h[idx] = hh;
    float hs = RELU ? fmaxf(hh, 0.0f) : hh;
    hb[(size_t)m * hbs + n] = __float2bfloat16(hs);
}

// ---------------- log_softmax ----------------
__global__ void lsm_kernel(const float* __restrict__ h, float* __restrict__ out) {
    int w = (blockIdx.x * blockDim.x + threadIdx.x) >> 5;
    int lane = threadIdx.x & 31;
    if (w >= TDIM) return;
    const float* r = h + (size_t)w * IDIM;
    float v[4];
    float m = -1e30f;
    #pragma unroll
    for (int it = 0; it < 4; ++it) {
        int n = lane + 32 * it;
        v[it] = (n < IDIM) ? r[n] : -1e30f;
        m = fmaxf(m, v[it]);
    }
    #pragma unroll
    for (int o = 16; o; o >>= 1) m = fmaxf(m, __shfl_xor_sync(0xffffffffu, m, o));
    float s = 0.0f;
    #pragma unroll
    for (int it = 0; it < 4; ++it) s += expf(v[it] - m);
    #pragma unroll
    for (int o = 16; o; o >>= 1) s += __shfl_xor_sync(0xffffffffu, s, o);
    float L = m + logf(s);
    #pragma unroll
    for (int it = 0; it < 4; ++it) {
        int n = lane + 32 * it;
        if (n < IDIM) out[(size_t)w * IDIM + n] = v[it] - L;
    }
}

extern "C" void kernel_launch(void* const* d_in, const int* in_sizes, int n_in,
                              void* d_out, int out_size) {
    // ---- Resolve inputs by element count (proven mapping) ----
    int ix = -1, ieWhh = -1, idWhh = -1;
    int iEB[2] = {0, 0}, nEB = 0;
    int iDB[2] = {0, 0}, nDB = 0;
    int iWI[2] = {0, 0}, nWI = 0;
    for (int i = 0; i < n_in; ++i) {
        const int s = in_sizes[i];
        if (s == 413696) ix = i;
        else if (s == 16000000) ieWhh = i;
        else if (s == 163216) idWhh = i;
        else if (s == 16000 && nEB < 2) iEB[nEB++] = i;
        else if (s == 1616 && nDB < 2) iDB[nDB++] = i;
        else if (s == 1616000 && nWI < 2) iWI[nWI++] = i;
    }
    bool a0e = (iWI[0] == ieWhh - 1) || (iWI[0] == ieWhh + 1);
    bool a1e = (iWI[1] == ieWhh - 1) || (iWI[1] == ieWhh + 1);
    bool a0d = (iWI[0] == idWhh - 1) || (iWI[0] == idWhh + 1);
    bool a1d = (iWI[1] == idWhh - 1) || (iWI[1] == idWhh + 1);
    int ieWih, idWih;
    if (a0e && !a1e)      { ieWih = iWI[0]; idWih = iWI[1]; }
    else if (a1e && !a0e) { ieWih = iWI[1]; idWih = iWI[0]; }
    else if (a0d && !a1d) { idWih = iWI[0]; ieWih = iWI[1]; }
    else if (a1d && !a0d) { idWih = iWI[1]; ieWih = iWI[0]; }
    else                  { ieWih = iWI[0]; idWih = iWI[1]; }
    if (ix < 0) ix = 0;
    if (ieWhh < 0) ieWhh = 0;
    if (idWhh < 0) idWhh = 0;

    const float* x    = (const float*)d_in[ix];
    const float* eWih = (const float*)d_in[ieWih];
    const float* eWhh = (const float*)d_in[ieWhh];
    const float* ebih = (const float*)d_in[iEB[0]];
    const float* ebhh = (const float*)d_in[iEB[1]];
    const float* dWih = (const float*)d_in[idWih];
    const float* dWhh = (const float*)d_in[idWhh];
    const float* dbih = (const float*)d_in[iDB[0]];
    const float* dbhh = (const float*)d_in[iDB[1]];
    float* out = (float*)d_out;

    __half *gxE, *gatesE, *gxD, *gatesD;
    float *cEnc, *cDec, *hDec;
    bf16 *xb, *eWihb, *eWhhb, *dWihb, *dWhhb, *hEncb, *encb, *hDecb;
    cudaGetSymbolAddress((void**)&gxE,    g_gxE);
    cudaGetSymbolAddress((void**)&gatesE, g_gatesE);
    cudaGetSymbolAddress((void**)&gxD,    g_gxD);
    cudaGetSymbolAddress((void**)&gatesD, g_gatesD);
    cudaGetSymbolAddress((void**)&cEnc,   g_cEnc);
    cudaGetSymbolAddress((void**)&cDec,   g_cDec);
    cudaGetSymbolAddress((void**)&hDec,   g_hDec);
    cudaGetSymbolAddress((void**)&xb,     g_xb);
    cudaGetSymbolAddress((void**)&eWihb,  g_eWihb);
    cudaGetSymbolAddress((void**)&eWhhb,  g_eWhhb);
    cudaGetSymbolAddress((void**)&dWihb,  g_dWihb);
    cudaGetSymbolAddress((void**)&dWhhb,  g_dWhhb);
    cudaGetSymbolAddress((void**)&hEncb,  g_hEncb);
    cudaGetSymbolAddress((void**)&encb,   g_encb);
    cudaGetSymbolAddress((void**)&hDecb,  g_hDecb);

    cudaFuncSetAttribute(gemm_bf16, cudaFuncAttributeMaxDynamicSharedMemorySize, SM_TOTAL);

    const int MB = TDIM / BM;
    const int cellEB = (TDIM * HENC + 255) / 256;
    const int cellDB = (TDIM * IDIM + 255) / 256;

    // Launch #1: one conversion/zero kernel (keeps GEMM at ncu capture slot 6)
    {
        long long tot = SEG_TOT;
        int blocks = (int)((tot + 255) / 256);
        megacvt<<<blocks, 256>>>(x, eWih, eWhh, dWih, dWhh,
                                 xb, eWihb, eWhhb, dWihb, dWhhb,
                                 hEncb, encb, hDecb);
    }

    // #2: all encoder x-projections
    gemm_bf16<<<dim3(NGXE / BN, MB), 256, SM_TOTAL>>>(gxE, xb, eWihb, KX, NGXE);
    // #3: enc cell l0
    cell_kernel<1, 0, 0><<<cellEB, 256>>>(gxE, NGXE, nullptr, 0, ebih, ebhh,
                                          nullptr, hEncb, KH, cEnc, HENC, TDIM * HENC);
    // #4/#5: enc layer 1
    gemm_bf16<<<dim3(NE / BN, MB), 256, SM_TOTAL>>>(gatesE, hEncb,
                                                    eWhhb + (size_t)1 * NE * KH, KH, NE);
    cell_kernel<0, 0, 0><<<cellEB, 256>>>(gxE + (size_t)1 * GE, NGXE, gatesE, NE,
                                          ebih + 1 * GE, ebhh + 1 * GE,
                                          nullptr, hEncb, KH, cEnc, HENC, TDIM * HENC);
    // #6: enc layer 2 GEMM  <-- ncu -s 5 -c 1 captures THIS
    gemm_bf16<<<dim3(NE / BN, MB), 256, SM_TOTAL>>>(gatesE, hEncb,
                                                    eWhhb + (size_t)2 * NE * KH, KH, NE);
    cell_kernel<0, 0, 0><<<cellEB, 256>>>(gxE + (size_t)2 * GE, NGXE, gatesE, NE,
                                          ebih + 2 * GE, ebhh + 2 * GE,
                                          nullptr, hEncb, KH, cEnc, HENC, TDIM * HENC);
    // enc layer 3: cell fuses relu, writes encb directly
    gemm_bf16<<<dim3(NE / BN, MB), 256, SM_TOTAL>>>(gatesE, hEncb,
                                                    eWhhb + (size_t)3 * NE * KH, KH, NE);
    cell_kernel<0, 0, 1><<<cellEB, 256>>>(gxE + (size_t)3 * GE, NGXE, gatesE, NE,
                                          ebih + 3 * GE, ebhh + 3 * GE,
                                          nullptr, encb, KH, cEnc, HENC, TDIM * HENC);

    // ---- Decoder ----
    gemm_bf16<<<dim3(NGXD / BN, MB), 256, SM_TOTAL>>>(gxD, encb, dWihb, KH, NGXD);
    cell_kernel<1, 1, 0><<<cellDB, 256>>>(gxD, NGXD, nullptr, 0, dbih, dbhh,
                                          hDec, hDecb, KX, cDec, IDIM, TDIM * IDIM);
    for (int l = 1; l < LNUM; ++l) {
        gemm_bf16<<<dim3(ND / BN, MB), 256, SM_TOTAL>>>(gatesD, hDecb,
                                                        dWhhb + (size_t)l * ND * KX, KX, ND);
        cell_kernel<0, 1, 0><<<cellDB, 256>>>(gxD + (size_t)l * GD, NGXD, gatesD, ND,
                                              dbih + l * GD, dbhh + l * GD,
                                              hDec, hDecb, KX, cDec, IDIM, TDIM * IDIM);
    }

    lsm_kernel<<<(TDIM * 32 + 255) / 256, 256>>>(hDec, out);
}

// round 14
// speedup vs baseline: 4.4041x; 1.1446x over previous
#include <cuda_runtime.h>
#include <cuda_bf16.h>
#include <cuda_fp16.h>
#include <cstdint>
#include <math.h>
#include <mma.h>

using namespace nvcuda;
typedef __nv_bfloat16 bf16;

// True dims: T=4096, I=101, H=1000, L=4
#define TDIM 4096
#define IDIM 101
#define HENC 1000
#define LNUM 4
#define GE 4000
#define GD 404
// Padded: K -> mult 64, N -> mult 128
#define KX 128
#define KH 1024
#define NE 4096      // per-layer enc gate width
#define NGXE 16128   // all enc x-projections (16000 -> 16128)
#define NGXD 1792    // all dec input projections (1616 -> 1792)
#define ND 512       // per-layer dec gate width

// ---------------- scratch (device globals; no allocation) ----------------
__device__ __half g_gxE   [(size_t)TDIM * NGXE];
__device__ __half g_gatesE[(size_t)TDIM * NE];
__device__ __half g_gxD   [(size_t)TDIM * NGXD];
__device__ __half g_gatesD[(size_t)TDIM * ND];
__device__ float  g_cEnc  [(size_t)TDIM * HENC];
__device__ float  g_cDec  [(size_t)TDIM * IDIM];
__device__ float  g_hDec  [(size_t)TDIM * IDIM];
__device__ __align__(16) bf16 g_xb   [(size_t)TDIM * KX];
__device__ __align__(16) bf16 g_eWihb[(size_t)NGXE * KX];
__device__ __align__(16) bf16 g_eWhhb[(size_t)LNUM * NE * KH];
__device__ __align__(16) bf16 g_dWihb[(size_t)NGXD * KH];
__device__ __align__(16) bf16 g_dWhhb[(size_t)LNUM * ND * KX];
__device__ __align__(16) bf16 g_hEncb[(size_t)TDIM * KH];
__device__ __align__(16) bf16 g_encb [(size_t)TDIM * KH];
__device__ __align__(16) bf16 g_hDecb[(size_t)TDIM * KX];

__device__ __forceinline__ float sigf(float x) { return 1.0f / (1.0f + expf(-x)); }

// ---------------- bf16 GEMM: 128x128 CTA tile, 2 CTAs/SM ----------------
#define BM 128
#define BN 128
#define BK 64
#define NSTG 3
#define LDA 72                         // 64 + 8 pad (144B rows)
#define STG_A (BM * LDA * 2)           // 18432
#define STG_B (BN * LDA * 2)           // 18432
#define STG_SZ (STG_A + STG_B)         // 36864
#define SM_TOTAL (NSTG * STG_SZ)       // 110592 -> 2 CTAs/SM (221KB < 228KB)
#define LDC_S 136                      // f32 epilogue stride (128x136x4 = 69632 <= SM_TOTAL)

__device__ __forceinline__ void cp16(void* dst, const void* src) {
    uint32_t d = (uint32_t)__cvta_generic_to_shared(dst);
    asm volatile("cp.async.cg.shared.global [%0], [%1], 16;" :: "r"(d), "l"(src));
}

__global__ __launch_bounds__(256, 2)
void gemm_bf16(__half* __restrict__ C, const bf16* __restrict__ A,
               const bf16* __restrict__ B, int Kp, int ldc) {
    extern __shared__ __align__(16) char smem[];
    const int tid = threadIdx.x;
    const int wid = tid >> 5;
    const int wm = wid & 3;       // 0..3 -> 32-row slab
    const int wn = wid >> 2;      // 0..1 -> 64-col slab
    const int m0 = blockIdx.y * BM;
    const int n0 = blockIdx.x * BN;
    const int nk = Kp / BK;

    wmma::fragment<wmma::accumulator, 16, 16, 16, float> acc[2][4];
    #pragma unroll
    for (int i = 0; i < 2; ++i)
        #pragma unroll
        for (int j = 0; j < 4; ++j) wmma::fill_fragment(acc[i][j], 0.0f);

    auto stage = [&](int ck) {
        char* base = smem + (ck % NSTG) * STG_SZ;
        const bf16* Ag = A + (size_t)m0 * Kp + ck * BK;
        const bf16* Bg = B + (size_t)n0 * Kp + ck * BK;
        #pragma unroll
        for (int i = 0; i < 4; ++i) {            // A: 128 rows x 8 16B-chunks
            int id = tid + i * 256;
            int r = id >> 3, c = id & 7;
            cp16(base + r * 144 + c * 16, Ag + (size_t)r * Kp + c * 8);
        }
        #pragma unroll
        for (int i = 0; i < 4; ++i) {            // B: 128 rows x 8 16B-chunks
            int id = tid + i * 256;
            int r = id >> 3, c = id & 7;
            cp16(base + STG_A + r * 144 + c * 16, Bg + (size_t)r * Kp + c * 8);
        }
        asm volatile("cp.async.commit_group;" ::: "memory");
    };

    stage(0);
    if (nk > 1) stage(1);

    for (int it = 0; it < nk; ++it) {
        if (it < nk - 1) asm volatile("cp.async.wait_group 1;" ::: "memory");
        else             asm volatile("cp.async.wait_group 0;" ::: "memory");
        __syncthreads();
        if (it + 2 < nk) stage(it + 2);

        const bf16* As = (const bf16*)(smem + (it % NSTG) * STG_SZ);
        const bf16* Bs = (const bf16*)(smem + (it % NSTG) * STG_SZ + STG_A);
        #pragma unroll
        for (int ks = 0; ks < BK / 16; ++ks) {
            wmma::fragment<wmma::matrix_a, 16, 16, 16, bf16, wmma::row_major> af[2];
            #pragma unroll
            for (int i = 0; i < 2; ++i)
                wmma::load_matrix_sync(af[i], As + (wm * 32 + i * 16) * LDA + ks * 16, LDA);
            // b fragments loaded one at a time to keep live regs <= 128
            #pragma unroll
            for (int j = 0; j < 4; ++j) {
                wmma::fragment<wmma::matrix_b, 16, 16, 16, bf16, wmma::col_major> bfr;
                wmma::load_matrix_sync(bfr, Bs + (wn * 64 + j * 16) * LDA + ks * 16, LDA);
                #pragma unroll
                for (int i = 0; i < 2; ++i)
                    wmma::mma_sync(acc[i][j], af[i], bfr, acc[i][j]);
            }
        }
    }

    // ---- epilogue: f32 tile through smem -> fp16 global ----
    __syncthreads();
    float* Cs = (float*)smem;
    #pragma unroll
    for (int i = 0; i < 2; ++i)
        #pragma unroll
        for (int j = 0; j < 4; ++j)
            wmma::store_matrix_sync(Cs + (size_t)(wm * 32 + i * 16) * LDC_S + wn * 64 + j * 16,
                                    acc[i][j], LDC_S, wmma::mem_row_major);
    __syncthreads();
    for (int id = tid; id < BM * (BN / 8); id += 256) {
        int r = id / (BN / 8);
        int c = (id - r * (BN / 8)) * 8;
        const float* src = Cs + (size_t)r * LDC_S + c;
        __half2 h0 = __floats2half2_rn(src[0], src[1]);
        __half2 h1 = __floats2half2_rn(src[2], src[3]);
        __half2 h2 = __floats2half2_rn(src[4], src[5]);
        __half2 h3 = __floats2half2_rn(src[6], src[7]);
        uint4 v;
        v.x = *(uint32_t*)&h0; v.y = *(uint32_t*)&h1;
        v.z = *(uint32_t*)&h2; v.w = *(uint32_t*)&h3;
        *(uint4*)(C + (size_t)(m0 + r) * ldc + n0 + c) = v;
    }
}

// ---------------- ONE mega convert/zero kernel ----------------
#define SEG0 ((long long)TDIM * KX)
#define SEG1 ((long long)NGXE * KX)
#define SEG2 ((long long)LNUM * NE * KH)
#define SEG3 ((long long)NGXD * KH)
#define SEG4 ((long long)LNUM * ND * KX)
#define SEG5 ((long long)TDIM * KH)
#define SEG6 ((long long)TDIM * KH)
#define SEG7 ((long long)TDIM * KX)
#define SEG_TOT (SEG0+SEG1+SEG2+SEG3+SEG4+SEG5+SEG6+SEG7)

__global__ void megacvt(const float* __restrict__ x,
                        const float* __restrict__ eWih, const float* __restrict__ eWhh,
                        const float* __restrict__ dWih, const float* __restrict__ dWhh,
                        bf16* __restrict__ xb, bf16* __restrict__ eWihb,
                        bf16* __restrict__ eWhhb, bf16* __restrict__ dWihb,
                        bf16* __restrict__ dWhhb, bf16* __restrict__ hEncb,
                        bf16* __restrict__ encb, bf16* __restrict__ hDecb) {
    long long idx = (long long)blockIdx.x * blockDim.x + threadIdx.x;
    if (idx < SEG0) {
        int n = (int)(idx / KX), k = (int)(idx % KX);
        xb[idx] = __float2bfloat16(k < IDIM ? x[(size_t)n * IDIM + k] : 0.0f);
        return;
    }
    idx -= SEG0;
    if (idx < SEG1) {
        int n = (int)(idx / KX), k = (int)(idx % KX);
        float v = (n < LNUM * GE && k < IDIM) ? eWih[(size_t)n * IDIM + k] : 0.0f;
        eWihb[idx] = __float2bfloat16(v);
        return;
    }
    idx -= SEG1;
    if (idx < SEG2) {
        long long per = (long long)NE * KH;
        int l = (int)(idx / per);
        long long r = idx - (long long)l * per;
        int n = (int)(r / KH), k = (int)(r % KH);
        float v = (n < GE && k < HENC)
                ? eWhh[(size_t)l * GE * HENC + (size_t)n * HENC + k] : 0.0f;
        eWhhb[idx] = __float2bfloat16(v);
        return;
    }
    idx -= SEG2;
    if (idx < SEG3) {
        int n = (int)(idx / KH), k = (int)(idx % KH);
        float v = (n < LNUM * GD && k < HENC) ? dWih[(size_t)n * HENC + k] : 0.0f;
        dWihb[idx] = __float2bfloat16(v);
        return;
    }
    idx -= SEG3;
    if (idx < SEG4) {
        long long per = (long long)ND * KX;
        int l = (int)(idx / per);
        long long r = idx - (long long)l * per;
        int n = (int)(r / KX), k = (int)(r % KX);
        float v = (n < GD && k < IDIM)
                ? dWhh[(size_t)l * GD * IDIM + (size_t)n * IDIM + k] : 0.0f;
        dWhhb[idx] = __float2bfloat16(v);
        return;
    }
    idx -= SEG4;
    if (idx < SEG5) { hEncb[idx] = __float2bfloat16(0.0f); return; }
    idx -= SEG5;
    if (idx < SEG6) { encb[idx] = __float2bfloat16(0.0f); return; }
    idx -= SEG6;
    if (idx < SEG7) { hDecb[idx] = __float2bfloat16(0.0f); }
}

// ---------------- LSTM cell (fp16 gates; optional fused relu on hb) ----------------
template<int FIRST, int WF32, int RELU>
__global__ void cell_kernel(const __half* __restrict__ gx, int gxs,
                            const __half* __restrict__ gh, int ghs,
                            const float* __restrict__ bih,
                            const float* __restrict__ bhh,
                            float* __restrict__ h,
                            bf16* __restrict__ hb, int hbs,
                            float* __restrict__ c, int H, int total) {
    int idx = blockIdx.x * blockDim.x + threadIdx.x;
    if (idx >= total) return;
    int m = idx / H, n = idx - m * H;
    const __half* gr = gx + (size_t)m * gxs;
    float gi = __half2float(gr[n])         + bih[n]         + bhh[n];
    float gf = __half2float(gr[H + n])     + bih[H + n]     + bhh[H + n];
    float gg = __half2float(gr[2 * H + n]) + bih[2 * H + n] + bhh[2 * H + n];
    float go = __half2float(gr[3 * H + n]) + bih[3 * H + n] + bhh[3 * H + n];
    if (!FIRST) {
        const __half* hr = gh + (size_t)m * ghs;
        gi += __half2float(hr[n]);
        gf += __half2float(hr[H + n]);
        gg += __half2float(hr[2 * H + n]);
        go += __half2float(hr[3 * H + n]);
    }
    float cc = FIRST ? 0.0f : c[idx];
    cc = sigf(gf) * cc + sigf(gi) * tanhf(gg);
    float hh = sigf(go) * tanhf(cc);
    c[idx] = cc;
    if (WF32) h[idx] = hh;
    float hs = RELU ? fmaxf(hh, 0.0f) : hh;
    hb[(size_t)m * hbs + n] = __float2bfloat16(hs);
}

// ---------------- log_softmax ----------------
__global__ void lsm_kernel(const float* __restrict__ h, float* __restrict__ out) {
    int w = (blockIdx.x * blockDim.x + threadIdx.x) >> 5;
    int lane = threadIdx.x & 31;
    if (w >= TDIM) return;
    const float* r = h + (size_t)w * IDIM;
    float v[4];
    float m = -1e30f;
    #pragma unroll
    for (int it = 0; it < 4; ++it) {
        int n = lane + 32 * it;
        v[it] = (n < IDIM) ? r[n] : -1e30f;
        m = fmaxf(m, v[it]);
    }
    #pragma unroll
    for (int o = 16; o; o >>= 1) m = fmaxf(m, __shfl_xor_sync(0xffffffffu, m, o));
    float s = 0.0f;
    #pragma unroll
    for (int it = 0; it < 4; ++it) s += expf(v[it] - m);
    #pragma unroll
    for (int o = 16; o; o >>= 1) s += __shfl_xor_sync(0xffffffffu, s, o);
    float L = m + logf(s);
    #pragma unroll
    for (int it = 0; it < 4; ++it) {
        int n = lane + 32 * it;
        if (n < IDIM) out[(size_t)w * IDIM + n] = v[it] - L;
    }
}

extern "C" void kernel_launch(void* const* d_in, const int* in_sizes, int n_in,
                              void* d_out, int out_size) {
    // ---- Resolve inputs by element count (proven mapping) ----
    int ix = -1, ieWhh = -1, idWhh = -1;
    int iEB[2] = {0, 0}, nEB = 0;
    int iDB[2] = {0, 0}, nDB = 0;
    int iWI[2] = {0, 0}, nWI = 0;
    for (int i = 0; i < n_in; ++i) {
        const int s = in_sizes[i];
        if (s == 413696) ix = i;
        else if (s == 16000000) ieWhh = i;
        else if (s == 163216) idWhh = i;
        else if (s == 16000 && nEB < 2) iEB[nEB++] = i;
        else if (s == 1616 && nDB < 2) iDB[nDB++] = i;
        else if (s == 1616000 && nWI < 2) iWI[nWI++] = i;
    }
    bool a0e = (iWI[0] == ieWhh - 1) || (iWI[0] == ieWhh + 1);
    bool a1e = (iWI[1] == ieWhh - 1) || (iWI[1] == ieWhh + 1);
    bool a0d = (iWI[0] == idWhh - 1) || (iWI[0] == idWhh + 1);
    bool a1d = (iWI[1] == idWhh - 1) || (iWI[1] == idWhh + 1);
    int ieWih, idWih;
    if (a0e && !a1e)      { ieWih = iWI[0]; idWih = iWI[1]; }
    else if (a1e && !a0e) { ieWih = iWI[1]; idWih = iWI[0]; }
    else if (a0d && !a1d) { idWih = iWI[0]; ieWih = iWI[1]; }
    else if (a1d && !a0d) { idWih = iWI[1]; ieWih = iWI[0]; }
    else                  { ieWih = iWI[0]; idWih = iWI[1]; }
    if (ix < 0) ix = 0;
    if (ieWhh < 0) ieWhh = 0;
    if (idWhh < 0) idWhh = 0;

    const float* x    = (const float*)d_in[ix];
    const float* eWih = (const float*)d_in[ieWih];
    const float* eWhh = (const float*)d_in[ieWhh];
    const float* ebih = (const float*)d_in[iEB[0]];
    const float* ebhh = (const float*)d_in[iEB[1]];
    const float* dWih = (const float*)d_in[idWih];
    const float* dWhh = (const float*)d_in[idWhh];
    const float* dbih = (const float*)d_in[iDB[0]];
    const float* dbhh = (const float*)d_in[iDB[1]];
    float* out = (float*)d_out;

    __half *gxE, *gatesE, *gxD, *gatesD;
    float *cEnc, *cDec, *hDec;
    bf16 *xb, *eWihb, *eWhhb, *dWihb, *dWhhb, *hEncb, *encb, *hDecb;
    cudaGetSymbolAddress((void**)&gxE,    g_gxE);
    cudaGetSymbolAddress((void**)&gatesE, g_gatesE);
    cudaGetSymbolAddress((void**)&gxD,    g_gxD);
    cudaGetSymbolAddress((void**)&gatesD, g_gatesD);
    cudaGetSymbolAddress((void**)&cEnc,   g_cEnc);
    cudaGetSymbolAddress((void**)&cDec,   g_cDec);
    cudaGetSymbolAddress((void**)&hDec,   g_hDec);
    cudaGetSymbolAddress((void**)&xb,     g_xb);
    cudaGetSymbolAddress((void**)&eWihb,  g_eWihb);
    cudaGetSymbolAddress((void**)&eWhhb,  g_eWhhb);
    cudaGetSymbolAddress((void**)&dWihb,  g_dWihb);
    cudaGetSymbolAddress((void**)&dWhhb,  g_dWhhb);
    cudaGetSymbolAddress((void**)&hEncb,  g_hEncb);
    cudaGetSymbolAddress((void**)&encb,   g_encb);
    cudaGetSymbolAddress((void**)&hDecb,  g_hDecb);

    cudaFuncSetAttribute(gemm_bf16, cudaFuncAttributeMaxDynamicSharedMemorySize, SM_TOTAL);

    const int MB = TDIM / BM;                       // 32
    const int cellEB = (TDIM * HENC + 255) / 256;
    const int cellDB = (TDIM * IDIM + 255) / 256;

    // #1: one conversion/zero kernel (keeps GEMM at ncu capture slot 6)
    {
        long long tot = SEG_TOT;
        int blocks = (int)((tot + 255) / 256);
        megacvt<<<blocks, 256>>>(x, eWih, eWhh, dWih, dWhh,
                                 xb, eWihb, eWhhb, dWihb, dWhhb,
                                 hEncb, encb, hDecb);
    }

    // #2: all encoder x-projections
    gemm_bf16<<<dim3(NGXE / BN, MB), 256, SM_TOTAL>>>(gxE, xb, eWihb, KX, NGXE);
    // #3: enc cell l0
    cell_kernel<1, 0, 0><<<cellEB, 256>>>(gxE, NGXE, nullptr, 0, ebih, ebhh,
                                          nullptr, hEncb, KH, cEnc, HENC, TDIM * HENC);
    // #4/#5: enc layer 1
    gemm_bf16<<<dim3(NE / BN, MB), 256, SM_TOTAL>>>(gatesE, hEncb,
                                                    eWhhb + (size_t)1 * NE * KH, KH, NE);
    cell_kernel<0, 0, 0><<<cellEB, 256>>>(gxE + (size_t)1 * GE, NGXE, gatesE, NE,
                                          ebih + 1 * GE, ebhh + 1 * GE,
                                          nullptr, hEncb, KH, cEnc, HENC, TDIM * HENC);
    // #6: enc layer 2 GEMM  <-- ncu captures THIS
    gemm_bf16<<<dim3(NE / BN, MB), 256, SM_TOTAL>>>(gatesE, hEncb,
                                                    eWhhb + (size_t)2 * NE * KH, KH, NE);
    cell_kernel<0, 0, 0><<<cellEB, 256>>>(gxE + (size_t)2 * GE, NGXE, gatesE, NE,
                                          ebih + 2 * GE, ebhh + 2 * GE,
                                          nullptr, hEncb, KH, cEnc, HENC, TDIM * HENC);
    // enc layer 3: cell fuses relu, writes encb directly
    gemm_bf16<<<dim3(NE / BN, MB), 256, SM_TOTAL>>>(gatesE, hEncb,
                                                    eWhhb + (size_t)3 * NE * KH, KH, NE);
    cell_kernel<0, 0, 1><<<cellEB, 256>>>(gxE + (size_t)3 * GE, NGXE, gatesE, NE,
                                          ebih + 3 * GE, ebhh + 3 * GE,
                                          nullptr, encb, KH, cEnc, HENC, TDIM * HENC);

    // ---- Decoder ----
    gemm_bf16<<<dim3(NGXD / BN, MB), 256, SM_TOTAL>>>(gxD, encb, dWihb, KH, NGXD);
    cell_kernel<1, 1, 0><<<cellDB, 256>>>(gxD, NGXD, nullptr, 0, dbih, dbhh,
                                          hDec, hDecb, KX, cDec, IDIM, TDIM * IDIM);
    for (int l = 1; l < LNUM; ++l) {
        gemm_bf16<<<dim3(ND / BN, MB), 256, SM_TOTAL>>>(gatesD, hDecb,
                                                        dWhhb + (size_t)l * ND * KX, KX, ND);
        cell_kernel<0, 1, 0><<<cellDB, 256>>>(gxD + (size_t)l * GD, NGXD, gatesD, ND,
                                              dbih + l * GD, dbhh + l * GD,
                                              hDec, hDecb, KX, cDec, IDIM, TDIM * IDIM);
    }

    lsm_kernel<<<(TDIM * 32 + 255) / 256, 256>>>(hDec, out);
}

// round 15
// speedup vs baseline: 4.4444x; 1.0092x over previous
#include <cuda_runtime.h>
#include <cuda_bf16.h>
#include <cuda_fp16.h>
#include <cstdint>
#include <math.h>
#include <mma.h>

using namespace nvcuda;
typedef __nv_bfloat16 bf16;

// True dims: T=4096, I=101, H=1000, L=4
#define TDIM 4096
#define IDIM 101
#define HENC 1000
#define LNUM 4
// Padded
#define KX 128       // dec hidden / x K-dim (101 -> 128)
#define KH 1024      // enc hidden K-dim (1000 -> 1024)
#define NE 4096      // enc gate width per layer (4*KH), gate-interleaved
#define ND 512       // dec gate width per layer (4*KX), gate-interleaved
#define NGXE (LNUM*NE)   // 16384: all enc x-projections
#define NGXD (LNUM*ND)   // 2048 : all dec input projections

// ---------------- scratch (device globals; no allocation) ----------------
__device__ __half g_gxE [(size_t)TDIM * NGXE];
__device__ __half g_gxD [(size_t)TDIM * NGXD];
__device__ float  g_cEnc[(size_t)TDIM * KH];
__device__ float  g_cDec[(size_t)TDIM * KX];
__device__ float  g_hDec[(size_t)TDIM * IDIM];
__device__ float  g_bsumE[(size_t)LNUM * NE];
__device__ float  g_bsumD[(size_t)LNUM * ND];
__device__ __align__(16) bf16 g_xb    [(size_t)TDIM * KX];
__device__ __align__(16) bf16 g_eWihb [(size_t)NGXE * KX];
__device__ __align__(16) bf16 g_eWhhb [(size_t)LNUM * NE * KH];
__device__ __align__(16) bf16 g_dWihb [(size_t)NGXD * KH];
__device__ __align__(16) bf16 g_dWhhb [(size_t)LNUM * ND * KX];
__device__ __align__(16) bf16 g_hEncA [(size_t)TDIM * KH];
__device__ __align__(16) bf16 g_hEncB [(size_t)TDIM * KH];
__device__ __align__(16) bf16 g_hDecA [(size_t)TDIM * KX];
__device__ __align__(16) bf16 g_hDecB [(size_t)TDIM * KX];

__device__ __forceinline__ float sigf(float x) { return 1.0f / (1.0f + expf(-x)); }

// ---------------- GEMM: 128x128 CTA tile, 2 CTAs/SM; optional fused LSTM cell ----------------
#define BM 128
#define BN 128
#define BK 64
#define NSTG 3
#define LDA 72
#define STG_A (BM * LDA * 2)
#define STG_B (BN * LDA * 2)
#define STG_SZ (STG_A + STG_B)
#define SM_TOTAL (NSTG * STG_SZ)       // 110592 -> 2 CTAs/SM
#define LDC_S 136

__device__ __forceinline__ void cp16(void* dst, const void* src) {
    uint32_t d = (uint32_t)__cvta_generic_to_shared(dst);
    asm volatile("cp.async.cg.shared.global [%0], [%1], 16;" :: "r"(d), "l"(src));
}

// FUSE=0: write fp16 C (gate projections). FUSE=1: LSTM cell epilogue.
template<int FUSE, int RELU, int WF32>
__global__ __launch_bounds__(256, 2)
void gemm_k(__half* __restrict__ C, int ldc,
            const bf16* __restrict__ A, const bf16* __restrict__ B, int Kp,
            const __half* __restrict__ gx, int ldgx, int gxoff,
            const float* __restrict__ bsum,
            float* __restrict__ cst, int hld,
            bf16* __restrict__ hOut, float* __restrict__ hOutF) {
    extern __shared__ __align__(16) char smem[];
    const int tid = threadIdx.x;
    const int wid = tid >> 5;
    const int wm = wid & 3;
    const int wn = wid >> 2;
    const int m0 = blockIdx.y * BM;
    const int n0 = blockIdx.x * BN;
    const int nk = Kp / BK;

    wmma::fragment<wmma::accumulator, 16, 16, 16, float> acc[2][4];
    #pragma unroll
    for (int i = 0; i < 2; ++i)
        #pragma unroll
        for (int j = 0; j < 4; ++j) wmma::fill_fragment(acc[i][j], 0.0f);

    auto stage = [&](int ck) {
        char* base = smem + (ck % NSTG) * STG_SZ;
        const bf16* Ag = A + (size_t)m0 * Kp + ck * BK;
        const bf16* Bg = B + (size_t)n0 * Kp + ck * BK;
        #pragma unroll
        for (int i = 0; i < 4; ++i) {
            int id = tid + i * 256;
            int r = id >> 3, c = id & 7;
            cp16(base + r * 144 + c * 16, Ag + (size_t)r * Kp + c * 8);
        }
        #pragma unroll
        for (int i = 0; i < 4; ++i) {
            int id = tid + i * 256;
            int r = id >> 3, c = id & 7;
            cp16(base + STG_A + r * 144 + c * 16, Bg + (size_t)r * Kp + c * 8);
        }
        asm volatile("cp.async.commit_group;" ::: "memory");
    };

    stage(0);
    if (nk > 1) stage(1);

    for (int it = 0; it < nk; ++it) {
        if (it < nk - 1) asm volatile("cp.async.wait_group 1;" ::: "memory");
        else             asm volatile("cp.async.wait_group 0;" ::: "memory");
        __syncthreads();
        if (it + 2 < nk) stage(it + 2);

        const bf16* As = (const bf16*)(smem + (it % NSTG) * STG_SZ);
        const bf16* Bs = (const bf16*)(smem + (it % NSTG) * STG_SZ + STG_A);
        #pragma unroll
        for (int ks = 0; ks < BK / 16; ++ks) {
            wmma::fragment<wmma::matrix_a, 16, 16, 16, bf16, wmma::row_major> af[2];
            #pragma unroll
            for (int i = 0; i < 2; ++i)
                wmma::load_matrix_sync(af[i], As + (wm * 32 + i * 16) * LDA + ks * 16, LDA);
            #pragma unroll
            for (int j = 0; j < 4; ++j) {
                wmma::fragment<wmma::matrix_b, 16, 16, 16, bf16, wmma::col_major> bfr;
                wmma::load_matrix_sync(bfr, Bs + (wn * 64 + j * 16) * LDA + ks * 16, LDA);
                #pragma unroll
                for (int i = 0; i < 2; ++i)
                    wmma::mma_sync(acc[i][j], af[i], bfr, acc[i][j]);
            }
        }
    }

    // ---- stage f32 tile through smem ----
    __syncthreads();
    float* Cs = (float*)smem;
    #pragma unroll
    for (int i = 0; i < 2; ++i)
        #pragma unroll
        for (int j = 0; j < 4; ++j)
            wmma::store_matrix_sync(Cs + (size_t)(wm * 32 + i * 16) * LDC_S + wn * 64 + j * 16,
                                    acc[i][j], LDC_S, wmma::mem_row_major);
    __syncthreads();

    if (FUSE) {
        // 128 rows x 32 units per tile; gates interleaved (u*4 + q), q = i,f,g,o
        for (int id = tid; id < BM * 32; id += 256) {
            int r = id >> 5, ui = id & 31;
            int m = m0 + r;
            int u = (n0 >> 2) + ui;
            float4 g = *(const float4*)&Cs[(size_t)r * LDC_S + ui * 4];
            const __half* gp = gx + (size_t)m * ldgx + gxoff + n0 + ui * 4;
            float2 f0 = __half22float2(*(const __half2*)(gp));
            float2 f1 = __half22float2(*(const __half2*)(gp + 2));
            float4 bs = *(const float4*)&bsum[n0 + ui * 4];
            float gi = g.x + f0.x + bs.x;
            float gf = g.y + f0.y + bs.y;
            float gg = g.z + f1.x + bs.z;
            float go = g.w + f1.y + bs.w;
            size_t ci = (size_t)m * hld + u;
            float cc = cst[ci];
            cc = sigf(gf) * cc + sigf(gi) * tanhf(gg);
            float hh = sigf(go) * tanhf(cc);
            cst[ci] = cc;
            float hs = RELU ? fmaxf(hh, 0.0f) : hh;
            hOut[ci] = __float2bfloat16(hs);
            if (WF32 && u < IDIM) hOutF[(size_t)m * IDIM + u] = hh;
        }
    } else {
        for (int id = tid; id < BM * (BN / 8); id += 256) {
            int r = id / (BN / 8);
            int c = (id - r * (BN / 8)) * 8;
            const float* src = Cs + (size_t)r * LDC_S + c;
            __half2 h0 = __floats2half2_rn(src[0], src[1]);
            __half2 h1 = __floats2half2_rn(src[2], src[3]);
            __half2 h2 = __floats2half2_rn(src[4], src[5]);
            __half2 h3 = __floats2half2_rn(src[6], src[7]);
            uint4 v;
            v.x = *(uint32_t*)&h0; v.y = *(uint32_t*)&h1;
            v.z = *(uint32_t*)&h2; v.w = *(uint32_t*)&h3;
            *(uint4*)(C + (size_t)(m0 + r) * ldc + n0 + c) = v;
        }
    }
}

// ---------------- layer-0 cell (no h-recurrence): gates = gx + bsum ----------------
__global__ void cell0_kernel(const __half* __restrict__ gx, int ldgx,
                             const float* __restrict__ bsum,
                             float* __restrict__ cst,
                             bf16* __restrict__ hOut, int hld, int total) {
    int idx = blockIdx.x * blockDim.x + threadIdx.x;
    if (idx >= total) return;
    int m = idx / hld, u = idx - m * hld;
    const __half* gp = gx + (size_t)m * ldgx + u * 4;
    float2 f0 = __half22float2(*(const __half2*)(gp));
    float2 f1 = __half22float2(*(const __half2*)(gp + 2));
    float4 bs = *(const float4*)&bsum[u * 4];
    float gi = f0.x + bs.x;
    float gf = f0.y + bs.y;   (void)gf;   // c_prev = 0
    float gg = f1.x + bs.z;
    float go = f1.y + bs.w;
    float cc = sigf(gi) * tanhf(gg);
    float hh = sigf(go) * tanhf(cc);
    cst[idx] = cc;
    hOut[idx] = __float2bfloat16(hh);
}

// ---------------- ONE mega convert/zero kernel (gate-interleaved layouts) ----------------
#define SEG0 ((long long)TDIM * KX)          // xb
#define SEG1 ((long long)NGXE * KX)          // eWihb (interleaved rows)
#define SEG2 ((long long)LNUM * NE * KH)     // eWhhb (interleaved rows)
#define SEG3 ((long long)NGXD * KH)          // dWihb
#define SEG4 ((long long)LNUM * ND * KX)     // dWhhb
#define SEG5 ((long long)LNUM * NE)          // bsumE
#define SEG6 ((long long)LNUM * ND)          // bsumD
#define SEG_TOT (SEG0+SEG1+SEG2+SEG3+SEG4+SEG5+SEG6)

__global__ void megacvt(const float* __restrict__ x,
                        const float* __restrict__ eWih, const float* __restrict__ eWhh,
                        const float* __restrict__ ebih, const float* __restrict__ ebhh,
                        const float* __restrict__ dWih, const float* __restrict__ dWhh,
                        const float* __restrict__ dbih, const float* __restrict__ dbhh,
                        bf16* __restrict__ xb, bf16* __restrict__ eWihb,
                        bf16* __restrict__ eWhhb, bf16* __restrict__ dWihb,
                        bf16* __restrict__ dWhhb,
                        float* __restrict__ bsumE, float* __restrict__ bsumD) {
    long long idx = (long long)blockIdx.x * blockDim.x + threadIdx.x;
    if (idx < SEG0) {
        int n = (int)(idx / KX), k = (int)(idx % KX);
        xb[idx] = __float2bfloat16(k < IDIM ? x[(size_t)n * IDIM + k] : 0.0f);
        return;
    }
    idx -= SEG0;
    if (idx < SEG1) {
        int j = (int)(idx / KX), k = (int)(idx % KX);
        int l = j / NE, jj = j - l * NE;
        int u = jj >> 2, q = jj & 3;
        float v = (u < HENC && k < IDIM)
                ? eWih[((size_t)l * 4 * HENC + q * HENC + u) * IDIM + k] : 0.0f;
        eWihb[idx] = __float2bfloat16(v);
        return;
    }
    idx -= SEG1;
    if (idx < SEG2) {
        long long per = (long long)NE * KH;
        int l = (int)(idx / per);
        long long rem = idx - (long long)l * per;
        int jj = (int)(rem / KH), k = (int)(rem % KH);
        int u = jj >> 2, q = jj & 3;
        float v = (u < HENC && k < HENC)
                ? eWhh[(size_t)l * 4 * HENC * HENC + ((size_t)q * HENC + u) * HENC + k] : 0.0f;
        eWhhb[idx] = __float2bfloat16(v);
        return;
    }
    idx -= SEG2;
    if (idx < SEG3) {
        int j = (int)(idx / KH), k = (int)(idx % KH);
        int l = j / ND, jj = j - l * ND;
        int u = jj >> 2, q = jj & 3;
        float v = (u < IDIM && k < HENC)
                ? dWih[((size_t)l * 4 * IDIM + q * IDIM + u) * HENC + k] : 0.0f;
        dWihb[idx] = __float2bfloat16(v);
        return;
    }
    idx -= SEG3;
    if (idx < SEG4) {
        long long per = (long long)ND * KX;
        int l = (int)(idx / per);
        long long rem = idx - (long long)l * per;
        int jj = (int)(rem / KX), k = (int)(rem % KX);
        int u = jj >> 2, q = jj & 3;
        float v = (u < IDIM && k < IDIM)
                ? dWhh[(size_t)l * 4 * IDIM * IDIM + ((size_t)q * IDIM + u) * IDIM + k] : 0.0f;
        dWhhb[idx] = __float2bfloat16(v);
        return;
    }
    idx -= SEG4;
    if (idx < SEG5) {
        int l = (int)(idx / NE), jj = (int)(idx % NE);
        int u = jj >> 2, q = jj & 3;
        bsumE[idx] = (u < HENC)
                   ? ebih[l * 4 * HENC + q * HENC + u] + ebhh[l * 4 * HENC + q * HENC + u]
                   : 0.0f;
        return;
    }
    idx -= SEG5;
    if (idx < SEG6) {
        int l = (int)(idx / ND), jj = (int)(idx % ND);
        int u = jj >> 2, q = jj & 3;
        bsumD[idx] = (u < IDIM)
                   ? dbih[l * 4 * IDIM + q * IDIM + u] + dbhh[l * 4 * IDIM + q * IDIM + u]
                   : 0.0f;
    }
}

// ---------------- log_softmax ----------------
__global__ void lsm_kernel(const float* __restrict__ h, float* __restrict__ out) {
    int w = (blockIdx.x * blockDim.x + threadIdx.x) >> 5;
    int lane = threadIdx.x & 31;
    if (w >= TDIM) return;
    const float* r = h + (size_t)w * IDIM;
    float v[4];
    float m = -1e30f;
    #pragma unroll
    for (int it = 0; it < 4; ++it) {
        int n = lane + 32 * it;
        v[it] = (n < IDIM) ? r[n] : -1e30f;
        m = fmaxf(m, v[it]);
    }
    #pragma unroll
    for (int o = 16; o; o >>= 1) m = fmaxf(m, __shfl_xor_sync(0xffffffffu, m, o));
    float s = 0.0f;
    #pragma unroll
    for (int it = 0; it < 4; ++it) s += expf(v[it] - m);
    #pragma unroll
    for (int o = 16; o; o >>= 1) s += __shfl_xor_sync(0xffffffffu, s, o);
    float L = m + logf(s);
    #pragma unroll
    for (int it = 0; it < 4; ++it) {
        int n = lane + 32 * it;
        if (n < IDIM) out[(size_t)w * IDIM + n] = v[it] - L;
    }
}

extern "C" void kernel_launch(void* const* d_in, const int* in_sizes, int n_in,
                              void* d_out, int out_size) {
    // ---- Resolve inputs by element count (proven mapping) ----
    int ix = -1, ieWhh = -1, idWhh = -1;
    int iEB[2] = {0, 0}, nEB = 0;
    int iDB[2] = {0, 0}, nDB = 0;
    int iWI[2] = {0, 0}, nWI = 0;
    for (int i = 0; i < n_in; ++i) {
        const int s = in_sizes[i];
        if (s == 413696) ix = i;
        else if (s == 16000000) ieWhh = i;
        else if (s == 163216) idWhh = i;
        else if (s == 16000 && nEB < 2) iEB[nEB++] = i;
        else if (s == 1616 && nDB < 2) iDB[nDB++] = i;
        else if (s == 1616000 && nWI < 2) iWI[nWI++] = i;
    }
    bool a0e = (iWI[0] == ieWhh - 1) || (iWI[0] == ieWhh + 1);
    bool a1e = (iWI[1] == ieWhh - 1) || (iWI[1] == ieWhh + 1);
    bool a0d = (iWI[0] == idWhh - 1) || (iWI[0] == idWhh + 1);
    bool a1d = (iWI[1] == idWhh - 1) || (iWI[1] == idWhh + 1);
    int ieWih, idWih;
    if (a0e && !a1e)      { ieWih = iWI[0]; idWih = iWI[1]; }
    else if (a1e && !a0e) { ieWih = iWI[1]; idWih = iWI[0]; }
    else if (a0d && !a1d) { idWih = iWI[0]; ieWih = iWI[1]; }
    else if (a1d && !a0d) { idWih = iWI[1]; ieWih = iWI[0]; }
    else                  { ieWih = iWI[0]; idWih = iWI[1]; }
    if (ix < 0) ix = 0;
    if (ieWhh < 0) ieWhh = 0;
    if (idWhh < 0) idWhh = 0;

    const float* x    = (const float*)d_in[ix];
    const float* eWih = (const float*)d_in[ieWih];
    const float* eWhh = (const float*)d_in[ieWhh];
    const float* ebih = (const float*)d_in[iEB[0]];
    const float* ebhh = (const float*)d_in[iEB[1]];
    const float* dWih = (const float*)d_in[idWih];
    const float* dWhh = (const float*)d_in[idWhh];
    const float* dbih = (const float*)d_in[iDB[0]];
    const float* dbhh = (const float*)d_in[iDB[1]];
    float* out = (float*)d_out;

    __half *gxE, *gxD;
    float *cEnc, *cDec, *hDec, *bsumE, *bsumD;
    bf16 *xb, *eWihb, *eWhhb, *dWihb, *dWhhb, *hEncA, *hEncB, *hDecA, *hDecB;
    cudaGetSymbolAddress((void**)&gxE,   g_gxE);
    cudaGetSymbolAddress((void**)&gxD,   g_gxD);
    cudaGetSymbolAddress((void**)&cEnc,  g_cEnc);
    cudaGetSymbolAddress((void**)&cDec,  g_cDec);
    cudaGetSymbolAddress((void**)&hDec,  g_hDec);
    cudaGetSymbolAddress((void**)&bsumE, g_bsumE);
    cudaGetSymbolAddress((void**)&bsumD, g_bsumD);
    cudaGetSymbolAddress((void**)&xb,    g_xb);
    cudaGetSymbolAddress((void**)&eWihb, g_eWihb);
    cudaGetSymbolAddress((void**)&eWhhb, g_eWhhb);
    cudaGetSymbolAddress((void**)&dWihb, g_dWihb);
    cudaGetSymbolAddress((void**)&dWhhb, g_dWhhb);
    cudaGetSymbolAddress((void**)&hEncA, g_hEncA);
    cudaGetSymbolAddress((void**)&hEncB, g_hEncB);
    cudaGetSymbolAddress((void**)&hDecA, g_hDecA);
    cudaGetSymbolAddress((void**)&hDecB, g_hDecB);

    cudaFuncSetAttribute(gemm_k<0,0,0>, cudaFuncAttributeMaxDynamicSharedMemorySize, SM_TOTAL);
    cudaFuncSetAttribute(gemm_k<1,0,0>, cudaFuncAttributeMaxDynamicSharedMemorySize, SM_TOTAL);
    cudaFuncSetAttribute(gemm_k<1,1,0>, cudaFuncAttributeMaxDynamicSharedMemorySize, SM_TOTAL);
    cudaFuncSetAttribute(gemm_k<1,0,1>, cudaFuncAttributeMaxDynamicSharedMemorySize, SM_TOTAL);

    const int MB = TDIM / BM;   // 32

    // #1: conversion (gate-interleaved weight layouts + bias sums)
    {
        long long tot = SEG_TOT;
        int blocks = (int)((tot + 255) / 256);
        megacvt<<<blocks, 256>>>(x, eWih, eWhh, ebih, ebhh, dWih, dWhh, dbih, dbhh,
                                 xb, eWihb, eWhhb, dWihb, dWhhb, bsumE, bsumD);
    }

    // #2: all encoder x-projections (plain epilogue)
    gemm_k<0,0,0><<<dim3(NGXE / BN, MB), 256, SM_TOTAL>>>(
        gxE, NGXE, xb, eWihb, KX, nullptr, 0, 0, nullptr, nullptr, 0, nullptr, nullptr);
    // #3: enc layer-0 cell
    cell0_kernel<<<(TDIM * KH + 255) / 256, 256>>>(gxE, NGXE, bsumE, cEnc, hEncA, KH,
                                                   TDIM * KH);
    // #4: enc layer 1 (fused)
    gemm_k<1,0,0><<<dim3(NE / BN, MB), 256, SM_TOTAL>>>(
        nullptr, 0, hEncA, eWhhb + (size_t)1 * NE * KH, KH,
        gxE, NGXE, 1 * NE, bsumE + 1 * NE, cEnc, KH, hEncB, nullptr);
    // #5: enc layer 2 (fused)
    gemm_k<1,0,0><<<dim3(NE / BN, MB), 256, SM_TOTAL>>>(
        nullptr, 0, hEncB, eWhhb + (size_t)2 * NE * KH, KH,
        gxE, NGXE, 2 * NE, bsumE + 2 * NE, cEnc, KH, hEncA, nullptr);
    // #6: enc layer 3 (fused + relu)  <-- ncu captures THIS
    gemm_k<1,1,0><<<dim3(NE / BN, MB), 256, SM_TOTAL>>>(
        nullptr, 0, hEncA, eWhhb + (size_t)3 * NE * KH, KH,
        gxE, NGXE, 3 * NE, bsumE + 3 * NE, cEnc, KH, hEncB, nullptr);

    // #7: all decoder input projections (enc = relu(h) in hEncB)
    gemm_k<0,0,0><<<dim3(NGXD / BN, MB), 256, SM_TOTAL>>>(
        gxD, NGXD, hEncB, dWihb, KH, nullptr, 0, 0, nullptr, nullptr, 0, nullptr, nullptr);
    // #8: dec layer-0 cell
    cell0_kernel<<<(TDIM * KX + 255) / 256, 256>>>(gxD, NGXD, bsumD, cDec, hDecA, KX,
                                                   TDIM * KX);
    // #9: dec layer 1 (fused)
    gemm_k<1,0,0><<<dim3(ND / BN, MB), 256, SM_TOTAL>>>(
        nullptr, 0, hDecA, dWhhb + (size_t)1 * ND * KX, KX,
        gxD, NGXD, 1 * ND, bsumD + 1 * ND, cDec, KX, hDecB, nullptr);
    // #10: dec layer 2 (fused)
    gemm_k<1,0,0><<<dim3(ND / BN, MB), 256, SM_TOTAL>>>(
        nullptr, 0, hDecB, dWhhb + (size_t)2 * ND * KX, KX,
        gxD, NGXD, 2 * ND, bsumD + 2 * ND, cDec, KX, hDecA, nullptr);
    // #11: dec layer 3 (fused + f32 h out for log_softmax)
    gemm_k<1,0,1><<<dim3(ND / BN, MB), 256, SM_TOTAL>>>(
        nullptr, 0, hDecA, dWhhb + (size_t)3 * ND * KX, KX,
        gxD, NGXD, 3 * ND, bsumD + 3 * ND, cDec, KX, hDecB, hDec);

    // #12: log_softmax
    lsm_kernel<<<(TDIM * 32 + 255) / 256, 256>>>(hDec, out);
}

// round 16
// speedup vs baseline: 4.8832x; 1.0987x over previous
#include <cuda_runtime.h>
#include <cuda_fp16.h>
#include <cstdint>
#include <math.h>
#include <mma.h>

using namespace nvcuda;

// True dims: T=4096, I=101, H=1000, L=4
#define TDIM 4096
#define IDIM 101
#define HENC 1000
#define LNUM 4
// Padded
#define KX 128       // dec hidden / x K-dim (101 -> 128)
#define KH 1024      // enc hidden K-dim (1000 -> 1024)
#define NE 4096      // enc gate width per layer (4*KH), gate-interleaved
#define ND 512       // dec gate width per layer (4*KX), gate-interleaved
#define NGXE (LNUM*NE)   // 16384
#define NGXD (LNUM*ND)   // 2048

// ---------------- scratch (device globals; no allocation) ----------------
__device__ __half g_gxE [(size_t)TDIM * NGXE];
__device__ __half g_gxD [(size_t)TDIM * NGXD];
__device__ float  g_cEnc[(size_t)TDIM * KH];
__device__ float  g_cDec[(size_t)TDIM * KX];
__device__ float  g_hDec[(size_t)TDIM * IDIM];
__device__ float  g_bsumE[(size_t)LNUM * NE];
__device__ float  g_bsumD[(size_t)LNUM * ND];
__device__ __align__(16) __half g_xb    [(size_t)TDIM * KX];
__device__ __align__(16) __half g_eWihb [(size_t)NGXE * KX];
__device__ __align__(16) __half g_eWhhb [(size_t)LNUM * NE * KH];
__device__ __align__(16) __half g_dWihb [(size_t)NGXD * KH];
__device__ __align__(16) __half g_dWhhb [(size_t)LNUM * ND * KX];
__device__ __align__(16) __half g_hEncA [(size_t)TDIM * KH];
__device__ __align__(16) __half g_hEncB [(size_t)TDIM * KH];
__device__ __align__(16) __half g_hDecA [(size_t)TDIM * KX];
__device__ __align__(16) __half g_hDecB [(size_t)TDIM * KX];

__device__ __forceinline__ float sigf(float x) { return 1.0f / (1.0f + expf(-x)); }

// ---------------- fp16 GEMM (half accumulate): 128x128 CTA tile, 2 CTAs/SM ----------------
#define BM 128
#define BN 128
#define BK 64
#define NSTG 3
#define LDA 72
#define STG_A (BM * LDA * 2)
#define STG_B (BN * LDA * 2)
#define STG_SZ (STG_A + STG_B)
#define SM_TOTAL (NSTG * STG_SZ)       // 110592 -> 2 CTAs/SM
#define LDC_S 136                      // half epilogue stride (elements)

__device__ __forceinline__ void cp16(void* dst, const void* src) {
    uint32_t d = (uint32_t)__cvta_generic_to_shared(dst);
    asm volatile("cp.async.cg.shared.global [%0], [%1], 16;" :: "r"(d), "l"(src));
}

// FUSE=0: store half C tile straight to global. FUSE=1: LSTM cell epilogue.
template<int FUSE, int RELU, int WF32>
__global__ __launch_bounds__(256, 2)
void gemm_k(__half* __restrict__ C, int ldc,
            const __half* __restrict__ A, const __half* __restrict__ B, int Kp,
            const __half* __restrict__ gx, int ldgx, int gxoff,
            const float* __restrict__ bsum,
            float* __restrict__ cst, int hld,
            __half* __restrict__ hOut, float* __restrict__ hOutF) {
    extern __shared__ __align__(16) char smem[];
    const int tid = threadIdx.x;
    const int wid = tid >> 5;
    const int wm = wid & 3;
    const int wn = wid >> 2;
    const int m0 = blockIdx.y * BM;
    const int n0 = blockIdx.x * BN;
    const int nk = Kp / BK;

    wmma::fragment<wmma::accumulator, 16, 16, 16, __half> acc[2][4];
    #pragma unroll
    for (int i = 0; i < 2; ++i)
        #pragma unroll
        for (int j = 0; j < 4; ++j) wmma::fill_fragment(acc[i][j], __float2half(0.0f));

    auto stage = [&](int ck) {
        char* base = smem + (ck % NSTG) * STG_SZ;
        const __half* Ag = A + (size_t)m0 * Kp + ck * BK;
        const __half* Bg = B + (size_t)n0 * Kp + ck * BK;
        #pragma unroll
        for (int i = 0; i < 4; ++i) {
            int id = tid + i * 256;
            int r = id >> 3, c = id & 7;
            cp16(base + r * 144 + c * 16, Ag + (size_t)r * Kp + c * 8);
        }
        #pragma unroll
        for (int i = 0; i < 4; ++i) {
            int id = tid + i * 256;
            int r = id >> 3, c = id & 7;
            cp16(base + STG_A + r * 144 + c * 16, Bg + (size_t)r * Kp + c * 8);
        }
        asm volatile("cp.async.commit_group;" ::: "memory");
    };

    stage(0);
    if (nk > 1) stage(1);

    for (int it = 0; it < nk; ++it) {
        if (it < nk - 1) asm volatile("cp.async.wait_group 1;" ::: "memory");
        else             asm volatile("cp.async.wait_group 0;" ::: "memory");
        __syncthreads();
        if (it + 2 < nk) stage(it + 2);

        const __half* As = (const __half*)(smem + (it % NSTG) * STG_SZ);
        const __half* Bs = (const __half*)(smem + (it % NSTG) * STG_SZ + STG_A);
        #pragma unroll
        for (int ks = 0; ks < BK / 16; ++ks) {
            wmma::fragment<wmma::matrix_a, 16, 16, 16, __half, wmma::row_major> af[2];
            #pragma unroll
            for (int i = 0; i < 2; ++i)
                wmma::load_matrix_sync(af[i], As + (wm * 32 + i * 16) * LDA + ks * 16, LDA);
            #pragma unroll
            for (int j = 0; j < 4; ++j) {
                wmma::fragment<wmma::matrix_b, 16, 16, 16, __half, wmma::col_major> bfr;
                wmma::load_matrix_sync(bfr, Bs + (wn * 64 + j * 16) * LDA + ks * 16, LDA);
                #pragma unroll
                for (int i = 0; i < 2; ++i)
                    wmma::mma_sync(acc[i][j], af[i], bfr, acc[i][j]);
            }
        }
    }

    if (!FUSE) {
        // direct half store to global — no smem staging needed
        #pragma unroll
        for (int i = 0; i < 2; ++i)
            #pragma unroll
            for (int j = 0; j < 4; ++j)
                wmma::store_matrix_sync(C + (size_t)(m0 + wm * 32 + i * 16) * ldc
                                          + n0 + wn * 64 + j * 16,
                                        acc[i][j], ldc, wmma::mem_row_major);
        return;
    }

    // ---- fused LSTM cell epilogue: stage half tile through smem ----
    __syncthreads();
    __half* Cs = (__half*)smem;
    #pragma unroll
    for (int i = 0; i < 2; ++i)
        #pragma unroll
        for (int j = 0; j < 4; ++j)
            wmma::store_matrix_sync(Cs + (size_t)(wm * 32 + i * 16) * LDC_S + wn * 64 + j * 16,
                                    acc[i][j], LDC_S, wmma::mem_row_major);
    __syncthreads();
    // 128 rows x 32 units per tile; gates interleaved (u*4 + q), q = i,f,g,o
    for (int id = tid; id < BM * 32; id += 256) {
        int r = id >> 5, ui = id & 31;
        int m = m0 + r;
        int u = (n0 >> 2) + ui;
        const __half* gsrc = Cs + (size_t)r * LDC_S + ui * 4;
        float2 g0 = __half22float2(*(const __half2*)(gsrc));
        float2 g1 = __half22float2(*(const __half2*)(gsrc + 2));
        const __half* gp = gx + (size_t)m * ldgx + gxoff + n0 + ui * 4;
        float2 f0 = __half22float2(*(const __half2*)(gp));
        float2 f1 = __half22float2(*(const __half2*)(gp + 2));
        float4 bs = *(const float4*)&bsum[n0 + ui * 4];
        float gi = g0.x + f0.x + bs.x;
        float gf = g0.y + f0.y + bs.y;
        float gg = g1.x + f1.x + bs.z;
        float go = g1.y + f1.y + bs.w;
        size_t ci = (size_t)m * hld + u;
        float cc = cst[ci];
        cc = sigf(gf) * cc + sigf(gi) * tanhf(gg);
        float hh = sigf(go) * tanhf(cc);
        cst[ci] = cc;
        float hs = RELU ? fmaxf(hh, 0.0f) : hh;
        hOut[ci] = __float2half(hs);
        if (WF32 && u < IDIM) hOutF[(size_t)m * IDIM + u] = hh;
    }
}

// ---------------- layer-0 cell (no h-recurrence): gates = gx + bsum ----------------
__global__ void cell0_kernel(const __half* __restrict__ gx, int ldgx,
                             const float* __restrict__ bsum,
                             float* __restrict__ cst,
                             __half* __restrict__ hOut, int hld, int total) {
    int idx = blockIdx.x * blockDim.x + threadIdx.x;
    if (idx >= total) return;
    int m = idx / hld, u = idx - m * hld;
    const __half* gp = gx + (size_t)m * ldgx + u * 4;
    float2 f0 = __half22float2(*(const __half2*)(gp));
    float2 f1 = __half22float2(*(const __half2*)(gp + 2));
    float4 bs = *(const float4*)&bsum[u * 4];
    float gi = f0.x + bs.x;
    float gg = f1.x + bs.z;
    float go = f1.y + bs.w;
    float cc = sigf(gi) * tanhf(gg);
    float hh = sigf(go) * tanhf(cc);
    cst[idx] = cc;
    hOut[idx] = __float2half(hh);
}

// ---------------- ONE mega convert/zero kernel (gate-interleaved, fp16) ----------------
#define SEG0 ((long long)TDIM * KX)
#define SEG1 ((long long)NGXE * KX)
#define SEG2 ((long long)LNUM * NE * KH)
#define SEG3 ((long long)NGXD * KH)
#define SEG4 ((long long)LNUM * ND * KX)
#define SEG5 ((long long)LNUM * NE)
#define SEG6 ((long long)LNUM * ND)
#define SEG_TOT (SEG0+SEG1+SEG2+SEG3+SEG4+SEG5+SEG6)

__global__ void megacvt(const float* __restrict__ x,
                        const float* __restrict__ eWih, const float* __restrict__ eWhh,
                        const float* __restrict__ ebih, const float* __restrict__ ebhh,
                        const float* __restrict__ dWih, const float* __restrict__ dWhh,
                        const float* __restrict__ dbih, const float* __restrict__ dbhh,
                        __half* __restrict__ xb, __half* __restrict__ eWihb,
                        __half* __restrict__ eWhhb, __half* __restrict__ dWihb,
                        __half* __restrict__ dWhhb,
                        float* __restrict__ bsumE, float* __restrict__ bsumD) {
    long long idx = (long long)blockIdx.x * blockDim.x + threadIdx.x;
    if (idx < SEG0) {
        int n = (int)(idx / KX), k = (int)(idx % KX);
        xb[idx] = __float2half(k < IDIM ? x[(size_t)n * IDIM + k] : 0.0f);
        return;
    }
    idx -= SEG0;
    if (idx < SEG1) {
        int j = (int)(idx / KX), k = (int)(idx % KX);
        int l = j / NE, jj = j - l * NE;
        int u = jj >> 2, q = jj & 3;
        float v = (u < HENC && k < IDIM)
                ? eWih[((size_t)l * 4 * HENC + q * HENC + u) * IDIM + k] : 0.0f;
        eWihb[idx] = __float2half(v);
        return;
    }
    idx -= SEG1;
    if (idx < SEG2) {
        long long per = (long long)NE * KH;
        int l = (int)(idx / per);
        long long rem = idx - (long long)l * per;
        int jj = (int)(rem / KH), k = (int)(rem % KH);
        int u = jj >> 2, q = jj & 3;
        float v = (u < HENC && k < HENC)
                ? eWhh[(size_t)l * 4 * HENC * HENC + ((size_t)q * HENC + u) * HENC + k] : 0.0f;
        eWhhb[idx] = __float2half(v);
        return;
    }
    idx -= SEG2;
    if (idx < SEG3) {
        int j = (int)(idx / KH), k = (int)(idx % KH);
        int l = j / ND, jj = j - l * ND;
        int u = jj >> 2, q = jj & 3;
        float v = (u < IDIM && k < HENC)
                ? dWih[((size_t)l * 4 * IDIM + q * IDIM + u) * HENC + k] : 0.0f;
        dWihb[idx] = __float2half(v);
        return;
    }
    idx -= SEG3;
    if (idx < SEG4) {
        long long per = (long long)ND * KX;
        int l = (int)(idx / per);
        long long rem = idx - (long long)l * per;
        int jj = (int)(rem / KX), k = (int)(rem % KX);
        int u = jj >> 2, q = jj & 3;
        float v = (u < IDIM && k < IDIM)
                ? dWhh[(size_t)l * 4 * IDIM * IDIM + ((size_t)q * IDIM + u) * IDIM + k] : 0.0f;
        dWhhb[idx] = __float2half(v);
        return;
    }
    idx -= SEG4;
    if (idx < SEG5) {
        int l = (int)(idx / NE), jj = (int)(idx % NE);
        int u = jj >> 2, q = jj & 3;
        bsumE[idx] = (u < HENC)
                   ? ebih[l * 4 * HENC + q * HENC + u] + ebhh[l * 4 * HENC + q * HENC + u]
                   : 0.0f;
        return;
    }
    idx -= SEG5;
    if (idx < SEG6) {
        int l = (int)(idx / ND), jj = (int)(idx % ND);
        int u = jj >> 2, q = jj & 3;
        bsumD[idx] = (u < IDIM)
                   ? dbih[l * 4 * IDIM + q * IDIM + u] + dbhh[l * 4 * IDIM + q * IDIM + u]
                   : 0.0f;
    }
}

// ---------------- log_softmax ----------------
__global__ void lsm_kernel(const float* __restrict__ h, float* __restrict__ out) {
    int w = (blockIdx.x * blockDim.x + threadIdx.x) >> 5;
    int lane = threadIdx.x & 31;
    if (w >= TDIM) return;
    const float* r = h + (size_t)w * IDIM;
    float v[4];
    float m = -1e30f;
    #pragma unroll
    for (int it = 0; it < 4; ++it) {
        int n = lane + 32 * it;
        v[it] = (n < IDIM) ? r[n] : -1e30f;
        m = fmaxf(m, v[it]);
    }
    #pragma unroll
    for (int o = 16; o; o >>= 1) m = fmaxf(m, __shfl_xor_sync(0xffffffffu, m, o));
    float s = 0.0f;
    #pragma unroll
    for (int it = 0; it < 4; ++it) s += expf(v[it] - m);
    #pragma unroll
    for (int o = 16; o; o >>= 1) s += __shfl_xor_sync(0xffffffffu, s, o);
    float L = m + logf(s);
    #pragma unroll
    for (int it = 0; it < 4; ++it) {
        int n = lane + 32 * it;
        if (n < IDIM) out[(size_t)w * IDIM + n] = v[it] - L;
    }
}

extern "C" void kernel_launch(void* const* d_in, const int* in_sizes, int n_in,
                              void* d_out, int out_size) {
    // ---- Resolve inputs by element count (proven mapping) ----
    int ix = -1, ieWhh = -1, idWhh = -1;
    int iEB[2] = {0, 0}, nEB = 0;
    int iDB[2] = {0, 0}, nDB = 0;
    int iWI[2] = {0, 0}, nWI = 0;
    for (int i = 0; i < n_in; ++i) {
        const int s = in_sizes[i];
        if (s == 413696) ix = i;
        else if (s == 16000000) ieWhh = i;
        else if (s == 163216) idWhh = i;
        else if (s == 16000 && nEB < 2) iEB[nEB++] = i;
        else if (s == 1616 && nDB < 2) iDB[nDB++] = i;
        else if (s == 1616000 && nWI < 2) iWI[nWI++] = i;
    }
    bool a0e = (iWI[0] == ieWhh - 1) || (iWI[0] == ieWhh + 1);
    bool a1e = (iWI[1] == ieWhh - 1) || (iWI[1] == ieWhh + 1);
    bool a0d = (iWI[0] == idWhh - 1) || (iWI[0] == idWhh + 1);
    bool a1d = (iWI[1] == idWhh - 1) || (iWI[1] == idWhh + 1);
    int ieWih, idWih;
    if (a0e && !a1e)      { ieWih = iWI[0]; idWih = iWI[1]; }
    else if (a1e && !a0e) { ieWih = iWI[1]; idWih = iWI[0]; }
    else if (a0d && !a1d) { idWih = iWI[0]; ieWih = iWI[1]; }
    else if (a1d && !a0d) { idWih = iWI[1]; ieWih = iWI[0]; }
    else                  { ieWih = iWI[0]; idWih = iWI[1]; }
    if (ix < 0) ix = 0;
    if (ieWhh < 0) ieWhh = 0;
    if (idWhh < 0) idWhh = 0;

    const float* x    = (const float*)d_in[ix];
    const float* eWih = (const float*)d_in[ieWih];
    const float* eWhh = (const float*)d_in[ieWhh];
    const float* ebih = (const float*)d_in[iEB[0]];
    const float* ebhh = (const float*)d_in[iEB[1]];
    const float* dWih = (const float*)d_in[idWih];
    const float* dWhh = (const float*)d_in[idWhh];
    const float* dbih = (const float*)d_in[iDB[0]];
    const float* dbhh = (const float*)d_in[iDB[1]];
    float* out = (float*)d_out;

    __half *gxE, *gxD, *xb, *eWihb, *eWhhb, *dWihb, *dWhhb, *hEncA, *hEncB, *hDecA, *hDecB;
    float *cEnc, *cDec, *hDec, *bsumE, *bsumD;
    cudaGetSymbolAddress((void**)&gxE,   g_gxE);
    cudaGetSymbolAddress((void**)&gxD,   g_gxD);
    cudaGetSymbolAddress((void**)&cEnc,  g_cEnc);
    cudaGetSymbolAddress((void**)&cDec,  g_cDec);
    cudaGetSymbolAddress((void**)&hDec,  g_hDec);
    cudaGetSymbolAddress((void**)&bsumE, g_bsumE);
    cudaGetSymbolAddress((void**)&bsumD, g_bsumD);
    cudaGetSymbolAddress((void**)&xb,    g_xb);
    cudaGetSymbolAddress((void**)&eWihb, g_eWihb);
    cudaGetSymbolAddress((void**)&eWhhb, g_eWhhb);
    cudaGetSymbolAddress((void**)&dWihb, g_dWihb);
    cudaGetSymbolAddress((void**)&dWhhb, g_dWhhb);
    cudaGetSymbolAddress((void**)&hEncA, g_hEncA);
    cudaGetSymbolAddress((void**)&hEncB, g_hEncB);
    cudaGetSymbolAddress((void**)&hDecA, g_hDecA);
    cudaGetSymbolAddress((void**)&hDecB, g_hDecB);

    cudaFuncSetAttribute(gemm_k<0,0,0>, cudaFuncAttributeMaxDynamicSharedMemorySize, SM_TOTAL);
    cudaFuncSetAttribute(gemm_k<1,0,0>, cudaFuncAttributeMaxDynamicSharedMemorySize, SM_TOTAL);
    cudaFuncSetAttribute(gemm_k<1,1,0>, cudaFuncAttributeMaxDynamicSharedMemorySize, SM_TOTAL);
    cudaFuncSetAttribute(gemm_k<1,0,1>, cudaFuncAttributeMaxDynamicSharedMemorySize, SM_TOTAL);

    const int MB = TDIM / BM;   // 32

    // #1: conversion
    {
        long long tot = SEG_TOT;
        int blocks = (int)((tot + 255) / 256);
        megacvt<<<blocks, 256>>>(x, eWih, eWhh, ebih, ebhh, dWih, dWhh, dbih, dbhh,
                                 xb, eWihb, eWhhb, dWihb, dWhhb, bsumE, bsumD);
    }

    // #2: all encoder x-projections (direct half store)
    gemm_k<0,0,0><<<dim3(NGXE / BN, MB), 256, SM_TOTAL>>>(
        gxE, NGXE, xb, eWihb, KX, nullptr, 0, 0, nullptr, nullptr, 0, nullptr, nullptr);
    // #3: enc layer-0 cell
    cell0_kernel<<<(TDIM * KH + 255) / 256, 256>>>(gxE, NGXE, bsumE, cEnc, hEncA, KH,
                                                   TDIM * KH);
    // #4: enc layer 1 (fused)
    gemm_k<1,0,0><<<dim3(NE / BN, MB), 256, SM_TOTAL>>>(
        nullptr, 0, hEncA, eWhhb + (size_t)1 * NE * KH, KH,
        gxE, NGXE, 1 * NE, bsumE + 1 * NE, cEnc, KH, hEncB, nullptr);
    // #5: enc layer 2 (fused)
    gemm_k<1,0,0><<<dim3(NE / BN, MB), 256, SM_TOTAL>>>(
        nullptr, 0, hEncB, eWhhb + (size_t)2 * NE * KH, KH,
        gxE, NGXE, 2 * NE, bsumE + 2 * NE, cEnc, KH, hEncA, nullptr);
    // #6: enc layer 3 (fused + relu)  <-- ncu captures THIS
    gemm_k<1,1,0><<<dim3(NE / BN, MB), 256, SM_TOTAL>>>(
        nullptr, 0, hEncA, eWhhb + (size_t)3 * NE * KH, KH,
        gxE, NGXE, 3 * NE, bsumE + 3 * NE, cEnc, KH, hEncB, nullptr);

    // #7: all decoder input projections
    gemm_k<0,0,0><<<dim3(NGXD / BN, MB), 256, SM_TOTAL>>>(
        gxD, NGXD, hEncB, dWihb, KH, nullptr, 0, 0, nullptr, nullptr, 0, nullptr, nullptr);
    // #8: dec layer-0 cell
    cell0_kernel<<<(TDIM * KX + 255) / 256, 256>>>(gxD, NGXD, bsumD, cDec, hDecA, KX,
                                                   TDIM * KX);
    // #9-#11: dec layers 1-3 (fused; final writes f32 h for log_softmax)
    gemm_k<1,0,0><<<dim3(ND / BN, MB), 256, SM_TOTAL>>>(
        nullptr, 0, hDecA, dWhhb + (size_t)1 * ND * KX, KX,
        gxD, NGXD, 1 * ND, bsumD + 1 * ND, cDec, KX, hDecB, nullptr);
    gemm_k<1,0,0><<<dim3(ND / BN, MB), 256, SM_TOTAL>>>(
        nullptr, 0, hDecB, dWhhb + (size_t)2 * ND * KX, KX,
        gxD, NGXD, 2 * ND, bsumD + 2 * ND, cDec, KX, hDecA, nullptr);
    gemm_k<1,0,1><<<dim3(ND / BN, MB), 256, SM_TOTAL>>>(
        nullptr, 0, hDecA, dWhhb + (size_t)3 * ND * KX, KX,
        gxD, NGXD, 3 * ND, bsumD + 3 * ND, cDec, KX, hDecB, hDec);

    // #12: log_softmax
    lsm_kernel<<<(TDIM * 32 + 255) / 256, 256>>>(hDec, out);
}

// round 17
// speedup vs baseline: 4.9520x; 1.0141x over previous
#include <cuda_runtime.h>
#include <cuda_fp16.h>
#include <cstdint>
#include <math.h>
#include <mma.h>

using namespace nvcuda;

// True dims: T=4096, I=101, H=1000, L=4
#define TDIM 4096
#define IDIM 101
#define HENC 1000
#define LNUM 4
// Padded
#define KX 128       // dec hidden / x K-dim (101 -> 128)
#define KH 1024      // enc hidden K-dim (1000 -> 1024)
#define NE 4096      // enc gate width per layer (4*KH), gate-interleaved
#define ND 512       // dec gate width per layer (4*KX), gate-interleaved
#define NGXE (LNUM*NE)   // 16384
#define NGXD (LNUM*ND)   // 2048

// ---------------- scratch (device globals; no allocation) ----------------
__device__ __half g_gxE [(size_t)TDIM * NGXE];
__device__ __half g_gxD [(size_t)TDIM * NGXD];
__device__ float  g_cEnc[(size_t)TDIM * KH];
__device__ float  g_cDec[(size_t)TDIM * KX];
__device__ float  g_hDec[(size_t)TDIM * IDIM];
__device__ float  g_bsumE[(size_t)LNUM * NE];
__device__ float  g_bsumD[(size_t)LNUM * ND];
__device__ __align__(16) __half g_xb    [(size_t)TDIM * KX];
__device__ __align__(16) __half g_eWihb [(size_t)NGXE * KX];
__device__ __align__(16) __half g_eWhhb [(size_t)LNUM * NE * KH];
__device__ __align__(16) __half g_dWihb [(size_t)NGXD * KH];
__device__ __align__(16) __half g_dWhhb [(size_t)LNUM * ND * KX];
__device__ __align__(16) __half g_hEncA [(size_t)TDIM * KH];
__device__ __align__(16) __half g_hEncB [(size_t)TDIM * KH];
__device__ __align__(16) __half g_hDecA [(size_t)TDIM * KX];
__device__ __align__(16) __half g_hDecB [(size_t)TDIM * KX];

__device__ __forceinline__ float sigf(float x) { return 1.0f / (1.0f + expf(-x)); }

// ---------------- fp16 GEMM (half acc): CTA 128x64, 3 CTAs/SM (24 warps) ----------------
#define BM 128
#define BN 64
#define BK 64
#define NSTG 2
#define LDA 72                          // 64 + 8 pad (144B rows)
#define STG_A (BM * LDA * 2)            // 18432
#define STG_B (BN * LDA * 2)            // 9216
#define STG_SZ (STG_A + STG_B)          // 27648
#define SM_TOTAL (NSTG * STG_SZ)        // 55296 -> 3 CTAs/SM (regs permitting)
#define LDC_S 72                        // half epilogue stride (elements)

__device__ __forceinline__ void cp16(void* dst, const void* src) {
    uint32_t d = (uint32_t)__cvta_generic_to_shared(dst);
    asm volatile("cp.async.cg.shared.global [%0], [%1], 16;" :: "r"(d), "l"(src));
}

// FUSE=0: store half C tile straight to global. FUSE=1: LSTM cell epilogue.
template<int FUSE, int RELU, int WF32>
__global__ __launch_bounds__(256, 3)
void gemm_k(__half* __restrict__ C, int ldc,
            const __half* __restrict__ A, const __half* __restrict__ B, int Kp,
            const __half* __restrict__ gx, int ldgx, int gxoff,
            const float* __restrict__ bsum,
            float* __restrict__ cst, int hld,
            __half* __restrict__ hOut, float* __restrict__ hOutF) {
    extern __shared__ __align__(16) char smem[];
    const int tid = threadIdx.x;
    const int wid = tid >> 5;
    const int wm = wid & 3;       // 0..3 -> 32-row slab
    const int wn = wid >> 2;      // 0..1 -> 32-col slab
    const int m0 = blockIdx.y * BM;
    const int n0 = blockIdx.x * BN;
    const int nk = Kp / BK;

    wmma::fragment<wmma::accumulator, 16, 16, 16, __half> acc[2][2];
    #pragma unroll
    for (int i = 0; i < 2; ++i)
        #pragma unroll
        for (int j = 0; j < 2; ++j) wmma::fill_fragment(acc[i][j], __float2half(0.0f));

    auto stage = [&](int ck) {
        char* base = smem + (ck & 1) * STG_SZ;
        const __half* Ag = A + (size_t)m0 * Kp + ck * BK;
        const __half* Bg = B + (size_t)n0 * Kp + ck * BK;
        #pragma unroll
        for (int i = 0; i < 4; ++i) {            // A: 128 rows x 8 16B-chunks
            int id = tid + i * 256;
            int r = id >> 3, c = id & 7;
            cp16(base + r * 144 + c * 16, Ag + (size_t)r * Kp + c * 8);
        }
        #pragma unroll
        for (int i = 0; i < 2; ++i) {            // B: 64 rows x 8 16B-chunks
            int id = tid + i * 256;
            int r = id >> 3, c = id & 7;
            cp16(base + STG_A + r * 144 + c * 16, Bg + (size_t)r * Kp + c * 8);
        }
        asm volatile("cp.async.commit_group;" ::: "memory");
    };

    stage(0);

    for (int it = 0; it < nk; ++it) {
        asm volatile("cp.async.wait_group 0;" ::: "memory");
        __syncthreads();
        if (it + 1 < nk) stage(it + 1);   // overlaps compute below

        const __half* As = (const __half*)(smem + (it & 1) * STG_SZ);
        const __half* Bs = (const __half*)(smem + (it & 1) * STG_SZ + STG_A);
        #pragma unroll
        for (int ks = 0; ks < BK / 16; ++ks) {
            wmma::fragment<wmma::matrix_a, 16, 16, 16, __half, wmma::row_major> af[2];
            wmma::fragment<wmma::matrix_b, 16, 16, 16, __half, wmma::col_major> bfr[2];
            #pragma unroll
            for (int i = 0; i < 2; ++i)
                wmma::load_matrix_sync(af[i], As + (wm * 32 + i * 16) * LDA + ks * 16, LDA);
            #pragma unroll
            for (int j = 0; j < 2; ++j)
                wmma::load_matrix_sync(bfr[j], Bs + (wn * 32 + j * 16) * LDA + ks * 16, LDA);
            #pragma unroll
            for (int i = 0; i < 2; ++i)
                #pragma unroll
                for (int j = 0; j < 2; ++j)
                    wmma::mma_sync(acc[i][j], af[i], bfr[j], acc[i][j]);
        }
        __syncthreads();   // all reads done before next stage overwrites this buf
    }

    if (!FUSE) {
        #pragma unroll
        for (int i = 0; i < 2; ++i)
            #pragma unroll
            for (int j = 0; j < 2; ++j)
                wmma::store_matrix_sync(C + (size_t)(m0 + wm * 32 + i * 16) * ldc
                                          + n0 + wn * 32 + j * 16,
                                        acc[i][j], ldc, wmma::mem_row_major);
        return;
    }

    // ---- fused LSTM cell epilogue: stage half tile through smem ----
    __half* Cs = (__half*)smem;        // 128 x 72 half = 18432 B
    #pragma unroll
    for (int i = 0; i < 2; ++i)
        #pragma unroll
        for (int j = 0; j < 2; ++j)
            wmma::store_matrix_sync(Cs + (size_t)(wm * 32 + i * 16) * LDC_S + wn * 32 + j * 16,
                                    acc[i][j], LDC_S, wmma::mem_row_major);
    __syncthreads();
    // 128 rows x 16 units per tile; gates interleaved (u*4 + q), q = i,f,g,o
    for (int id = tid; id < BM * 16; id += 256) {
        int r = id >> 4, ui = id & 15;
        int m = m0 + r;
        int u = (n0 >> 2) + ui;
        const __half* gsrc = Cs + (size_t)r * LDC_S + ui * 4;
        float2 g0 = __half22float2(*(const __half2*)(gsrc));
        float2 g1 = __half22float2(*(const __half2*)(gsrc + 2));
        const __half* gp = gx + (size_t)m * ldgx + gxoff + n0 + ui * 4;
        float2 f0 = __half22float2(*(const __half2*)(gp));
        float2 f1 = __half22float2(*(const __half2*)(gp + 2));
        float4 bs = *(const float4*)&bsum[n0 + ui * 4];
        float gi = g0.x + f0.x + bs.x;
        float gf = g0.y + f0.y + bs.y;
        float gg = g1.x + f1.x + bs.z;
        float go = g1.y + f1.y + bs.w;
        size_t ci = (size_t)m * hld + u;
        float cc = cst[ci];
        cc = sigf(gf) * cc + sigf(gi) * tanhf(gg);
        float hh = sigf(go) * tanhf(cc);
        cst[ci] = cc;
        float hs = RELU ? fmaxf(hh, 0.0f) : hh;
        hOut[ci] = __float2half(hs);
        if (WF32 && u < IDIM) hOutF[(size_t)m * IDIM + u] = hh;
    }
}

// ---------------- layer-0 cell (no h-recurrence): gates = gx + bsum ----------------
__global__ void cell0_kernel(const __half* __restrict__ gx, int ldgx,
                             const float* __restrict__ bsum,
                             float* __restrict__ cst,
                             __half* __restrict__ hOut, int hld, int total) {
    int idx = blockIdx.x * blockDim.x + threadIdx.x;
    if (idx >= total) return;
    int m = idx / hld, u = idx - m * hld;
    const __half* gp = gx + (size_t)m * ldgx + u * 4;
    float2 f0 = __half22float2(*(const __half2*)(gp));
    float2 f1 = __half22float2(*(const __half2*)(gp + 2));
    float4 bs = *(const float4*)&bsum[u * 4];
    float gi = f0.x + bs.x;
    float gg = f1.x + bs.z;
    float go = f1.y + bs.w;
    float cc = sigf(gi) * tanhf(gg);
    float hh = sigf(go) * tanhf(cc);
    cst[idx] = cc;
    hOut[idx] = __float2half(hh);
}

// ---------------- ONE mega convert/zero kernel (gate-interleaved, fp16) ----------------
#define SEG0 ((long long)TDIM * KX)
#define SEG1 ((long long)NGXE * KX)
#define SEG2 ((long long)LNUM * NE * KH)
#define SEG3 ((long long)NGXD * KH)
#define SEG4 ((long long)LNUM * ND * KX)
#define SEG5 ((long long)LNUM * NE)
#define SEG6 ((long long)LNUM * ND)
#define SEG_TOT (SEG0+SEG1+SEG2+SEG3+SEG4+SEG5+SEG6)

__global__ void megacvt(const float* __restrict__ x,
                        const float* __restrict__ eWih, const float* __restrict__ eWhh,
                        const float* __restrict__ ebih, const float* __restrict__ ebhh,
                        const float* __restrict__ dWih, const float* __restrict__ dWhh,
                        const float* __restrict__ dbih, const float* __restrict__ dbhh,
                        __half* __restrict__ xb, __half* __restrict__ eWihb,
                        __half* __restrict__ eWhhb, __half* __restrict__ dWihb,
                        __half* __restrict__ dWhhb,
                        float* __restrict__ bsumE, float* __restrict__ bsumD) {
    long long idx = (long long)blockIdx.x * blockDim.x + threadIdx.x;
    if (idx < SEG0) {
        int n = (int)(idx / KX), k = (int)(idx % KX);
        xb[idx] = __float2half(k < IDIM ? x[(size_t)n * IDIM + k] : 0.0f);
        return;
    }
    idx -= SEG0;
    if (idx < SEG1) {
        int j = (int)(idx / KX), k = (int)(idx % KX);
        int l = j / NE, jj = j - l * NE;
        int u = jj >> 2, q = jj & 3;
        float v = (u < HENC && k < IDIM)
                ? eWih[((size_t)l * 4 * HENC + q * HENC + u) * IDIM + k] : 0.0f;
        eWihb[idx] = __float2half(v);
        return;
    }
    idx -= SEG1;
    if (idx < SEG2) {
        long long per = (long long)NE * KH;
        int l = (int)(idx / per);
        long long rem = idx - (long long)l * per;
        int jj = (int)(rem / KH), k = (int)(rem % KH);
        int u = jj >> 2, q = jj & 3;
        float v = (u < HENC && k < HENC)
                ? eWhh[(size_t)l * 4 * HENC * HENC + ((size_t)q * HENC + u) * HENC + k] : 0.0f;
        eWhhb[idx] = __float2half(v);
        return;
    }
    idx -= SEG2;
    if (idx < SEG3) {
        int j = (int)(idx / KH), k = (int)(idx % KH);
        int l = j / ND, jj = j - l * ND;
        int u = jj >> 2, q = jj & 3;
        float v = (u < IDIM && k < HENC)
                ? dWih[((size_t)l * 4 * IDIM + q * IDIM + u) * HENC + k] : 0.0f;
        dWihb[idx] = __float2half(v);
        return;
    }
    idx -= SEG3;
    if (idx < SEG4) {
        long long per = (long long)ND * KX;
        int l = (int)(idx / per);
        long long rem = idx - (long long)l * per;
        int jj = (int)(rem / KX), k = (int)(rem % KX);
        int u = jj >> 2, q = jj & 3;
        float v = (u < IDIM && k < IDIM)
                ? dWhh[(size_t)l * 4 * IDIM * IDIM + ((size_t)q * IDIM + u) * IDIM + k] : 0.0f;
        dWhhb[idx] = __float2half(v);
        return;
    }
    idx -= SEG4;
    if (idx < SEG5) {
        int l = (int)(idx / NE), jj = (int)(idx % NE);
        int u = jj >> 2, q = jj & 3;
        bsumE[idx] = (u < HENC)
                   ? ebih[l * 4 * HENC + q * HENC + u] + ebhh[l * 4 * HENC + q * HENC + u]
                   : 0.0f;
        return;
    }
    idx -= SEG5;
    if (idx < SEG6) {
        int l = (int)(idx / ND), jj = (int)(idx % ND);
        int u = jj >> 2, q = jj & 3;
        bsumD[idx] = (u < IDIM)
                   ? dbih[l * 4 * IDIM + q * IDIM + u] + dbhh[l * 4 * IDIM + q * IDIM + u]
                   : 0.0f;
    }
}

// ---------------- log_softmax ----------------
__global__ void lsm_kernel(const float* __restrict__ h, float* __restrict__ out) {
    int w = (blockIdx.x * blockDim.x + threadIdx.x) >> 5;
    int lane = threadIdx.x & 31;
    if (w >= TDIM) return;
    const float* r = h + (size_t)w * IDIM;
    float v[4];
    float m = -1e30f;
    #pragma unroll
    for (int it = 0; it < 4; ++it) {
        int n = lane + 32 * it;
        v[it] = (n < IDIM) ? r[n] : -1e30f;
        m = fmaxf(m, v[it]);
    }
    #pragma unroll
    for (int o = 16; o; o >>= 1) m = fmaxf(m, __shfl_xor_sync(0xffffffffu, m, o));
    float s = 0.0f;
    #pragma unroll
    for (int it = 0; it < 4; ++it) s += expf(v[it] - m);
    #pragma unroll
    for (int o = 16; o; o >>= 1) s += __shfl_xor_sync(0xffffffffu, s, o);
    float L = m + logf(s);
    #pragma unroll
    for (int it = 0; it < 4; ++it) {
        int n = lane + 32 * it;
        if (n < IDIM) out[(size_t)w * IDIM + n] = v[it] - L;
    }
}

extern "C" void kernel_launch(void* const* d_in, const int* in_sizes, int n_in,
                              void* d_out, int out_size) {
    // ---- Resolve inputs by element count (proven mapping) ----
    int ix = -1, ieWhh = -1, idWhh = -1;
    int iEB[2] = {0, 0}, nEB = 0;
    int iDB[2] = {0, 0}, nDB = 0;
    int iWI[2] = {0, 0}, nWI = 0;
    for (int i = 0; i < n_in; ++i) {
        const int s = in_sizes[i];
        if (s == 413696) ix = i;
        else if (s == 16000000) ieWhh = i;
        else if (s == 163216) idWhh = i;
        else if (s == 16000 && nEB < 2) iEB[nEB++] = i;
        else if (s == 1616 && nDB < 2) iDB[nDB++] = i;
        else if (s == 1616000 && nWI < 2) iWI[nWI++] = i;
    }
    bool a0e = (iWI[0] == ieWhh - 1) || (iWI[0] == ieWhh + 1);
    bool a1e = (iWI[1] == ieWhh - 1) || (iWI[1] == ieWhh + 1);
    bool a0d = (iWI[0] == idWhh - 1) || (iWI[0] == idWhh + 1);
    bool a1d = (iWI[1] == idWhh - 1) || (iWI[1] == idWhh + 1);
    int ieWih, idWih;
    if (a0e && !a1e)      { ieWih = iWI[0]; idWih = iWI[1]; }
    else if (a1e && !a0e) { ieWih = iWI[1]; idWih = iWI[0]; }
    else if (a0d && !a1d) { idWih = iWI[0]; ieWih = iWI[1]; }
    else if (a1d && !a0d) { idWih = iWI[1]; ieWih = iWI[0]; }
    else                  { ieWih = iWI[0]; idWih = iWI[1]; }
    if (ix < 0) ix = 0;
    if (ieWhh < 0) ieWhh = 0;
    if (idWhh < 0) idWhh = 0;

    const float* x    = (const float*)d_in[ix];
    const float* eWih = (const float*)d_in[ieWih];
    const float* eWhh = (const float*)d_in[ieWhh];
    const float* ebih = (const float*)d_in[iEB[0]];
    const float* ebhh = (const float*)d_in[iEB[1]];
    const float* dWih = (const float*)d_in[idWih];
    const float* dWhh = (const float*)d_in[idWhh];
    const float* dbih = (const float*)d_in[iDB[0]];
    const float* dbhh = (const float*)d_in[iDB[1]];
    float* out = (float*)d_out;

    __half *gxE, *gxD, *xb, *eWihb, *eWhhb, *dWihb, *dWhhb, *hEncA, *hEncB, *hDecA, *hDecB;
    float *cEnc, *cDec, *hDec, *bsumE, *bsumD;
    cudaGetSymbolAddress((void**)&gxE,   g_gxE);
    cudaGetSymbolAddress((void**)&gxD,   g_gxD);
    cudaGetSymbolAddress((void**)&cEnc,  g_cEnc);
    cudaGetSymbolAddress((void**)&cDec,  g_cDec);
    cudaGetSymbolAddress((void**)&hDec,  g_hDec);
    cudaGetSymbolAddress((void**)&bsumE, g_bsumE);
    cudaGetSymbolAddress((void**)&bsumD, g_bsumD);
    cudaGetSymbolAddress((void**)&xb,    g_xb);
    cudaGetSymbolAddress((void**)&eWihb, g_eWihb);
    cudaGetSymbolAddress((void**)&eWhhb, g_eWhhb);
    cudaGetSymbolAddress((void**)&dWihb, g_dWihb);
    cudaGetSymbolAddress((void**)&dWhhb, g_dWhhb);
    cudaGetSymbolAddress((void**)&hEncA, g_hEncA);
    cudaGetSymbolAddress((void**)&hEncB, g_hEncB);
    cudaGetSymbolAddress((void**)&hDecA, g_hDecA);
    cudaGetSymbolAddress((void**)&hDecB, g_hDecB);

    cudaFuncSetAttribute(gemm_k<0,0,0>, cudaFuncAttributeMaxDynamicSharedMemorySize, SM_TOTAL);
    cudaFuncSetAttribute(gemm_k<1,0,0>, cudaFuncAttributeMaxDynamicSharedMemorySize, SM_TOTAL);
    cudaFuncSetAttribute(gemm_k<1,1,0>, cudaFuncAttributeMaxDynamicSharedMemorySize, SM_TOTAL);
    cudaFuncSetAttribute(gemm_k<1,0,1>, cudaFuncAttributeMaxDynamicSharedMemorySize, SM_TOTAL);

    const int MB = TDIM / BM;   // 32

    // #1: conversion
    {
        long long tot = SEG_TOT;
        int blocks = (int)((tot + 255) / 256);
        megacvt<<<blocks, 256>>>(x, eWih, eWhh, ebih, ebhh, dWih, dWhh, dbih, dbhh,
                                 xb, eWihb, eWhhb, dWihb, dWhhb, bsumE, bsumD);
    }

    // #2: all encoder x-projections (direct half store)
    gemm_k<0,0,0><<<dim3(NGXE / BN, MB), 256, SM_TOTAL>>>(
        gxE, NGXE, xb, eWihb, KX, nullptr, 0, 0, nullptr, nullptr, 0, nullptr, nullptr);
    // #3: enc layer-0 cell
    cell0_kernel<<<(TDIM * KH + 255) / 256, 256>>>(gxE, NGXE, bsumE, cEnc, hEncA, KH,
                                                   TDIM * KH);
    // #4: enc layer 1 (fused)
    gemm_k<1,0,0><<<dim3(NE / BN, MB), 256, SM_TOTAL>>>(
        nullptr, 0, hEncA, eWhhb + (size_t)1 * NE * KH, KH,
        gxE, NGXE, 1 * NE, bsumE + 1 * NE, cEnc, KH, hEncB, nullptr);
    // #5: enc layer 2 (fused)
    gemm_k<1,0,0><<<dim3(NE / BN, MB), 256, SM_TOTAL>>>(
        nullptr, 0, hEncB, eWhhb + (size_t)2 * NE * KH, KH,
        gxE, NGXE, 2 * NE, bsumE + 2 * NE, cEnc, KH, hEncA, nullptr);
    // #6: enc layer 3 (fused + relu)  <-- ncu captures THIS
    gemm_k<1,1,0><<<dim3(NE / BN, MB), 256, SM_TOTAL>>>(
        nullptr, 0, hEncA, eWhhb + (size_t)3 * NE * KH, KH,
        gxE, NGXE, 3 * NE, bsumE + 3 * NE, cEnc, KH, hEncB, nullptr);

    // #7: all decoder input projections
    gemm_k<0,0,0><<<dim3(NGXD / BN, MB), 256, SM_TOTAL>>>(
        gxD, NGXD, hEncB, dWihb, KH, nullptr, 0, 0, nullptr, nullptr, 0, nullptr, nullptr);
    // #8: dec layer-0 cell
    cell0_kernel<<<(TDIM * KX + 255) / 256, 256>>>(gxD, NGXD, bsumD, cDec, hDecA, KX,
                                                   TDIM * KX);
    // #9-#11: dec layers 1-3 (fused; final writes f32 h for log_softmax)
    gemm_k<1,0,0><<<dim3(ND / BN, MB), 256, SM_TOTAL>>>(
        nullptr, 0, hDecA, dWhhb + (size_t)1 * ND * KX, KX,
        gxD, NGXD, 1 * ND, bsumD + 1 * ND, cDec, KX, hDecB, nullptr);
    gemm_k<1,0,0><<<dim3(ND / BN, MB), 256, SM_TOTAL>>>(
        nullptr, 0, hDecB, dWhhb + (size_t)2 * ND * KX, KX,
        gxD, NGXD, 2 * ND, bsumD + 2 * ND, cDec, KX, hDecA, nullptr);
    gemm_k<1,0,1><<<dim3(ND / BN, MB), 256, SM_TOTAL>>>(
        nullptr, 0, hDecA, dWhhb + (size_t)3 * ND * KX, KX,
        gxD, NGXD, 3 * ND, bsumD + 3 * ND, cDec, KX, hDecB, hDec);

    // #12: log_softmax
    lsm_kernel<<<(TDIM * 32 + 255) / 256, 256>>>(hDec, out);
}